// round 10
// baseline (speedup 1.0000x reference)
#include <cuda_runtime.h>
#include <cstdint>

#define NN 100000
#define KK 2
#define EMAX 1600000
#define SCAN_CHUNK 512
#define NB_SCAN ((NN + SCAN_CHUNK - 1) / SCAN_CHUNK)   // 196

// ---------------- scratch (static device globals; no allocation) -------------
__device__ float g_dinv[NN];
__device__ int   g_cnt[NN];
__device__ int   g_off[NN + 1];
__device__ int   g_cur[NN];
__device__ int   g_bsum[256];
__device__ int   g_boff[256];
__device__ int2  g_edge[EMAX];                        // (row, norm), CSR by col
__device__ float g_bufT[(size_t)KK * NN * 64 + 64];   // 51.2 MB
__device__ float g_bufA[(size_t)KK * NN * 64 + 64];   // 51.2 MB
__device__ uint2 g_xsplit[(size_t)NN * 128 + 64];     // 102.4 MB (tf32 hi/lo)
__device__ uint2 g_hsplit[(size_t)NN * 64 + 64];      // 51.2 MB (tf32 hi/lo)

__device__ __forceinline__ float* sel_buf(int s) {
    return s == 0 ? g_bufT : g_bufA;
}

// ---------------- tf32 helpers -----------------------------------------------
__device__ __forceinline__ uint32_t f2tf(float f) {
    uint32_t r;
    asm("cvt.rna.tf32.f32 %0, %1;" : "=r"(r) : "f"(f));
    return r;
}

__device__ __forceinline__ void mma8(float* d, const uint32_t* a,
                                     uint32_t b0, uint32_t b1) {
    asm("mma.sync.aligned.m16n8k8.row.col.f32.tf32.tf32.f32 "
        "{%0,%1,%2,%3}, {%4,%5,%6,%7}, {%8,%9}, {%0,%1,%2,%3};"
        : "+f"(d[0]), "+f"(d[1]), "+f"(d[2]), "+f"(d[3])
        : "r"(a[0]), "r"(a[1]), "r"(a[2]), "r"(a[3]), "r"(b0), "r"(b1));
}

// ---------------- prep: degree, CSR build ------------------------------------
__global__ void zero_cnt_kernel() {
    int n = blockIdx.x * blockDim.x + threadIdx.x;
    if (n < NN) g_cnt[n] = 0;
}

__global__ void count_kernel(const int* __restrict__ col, int E) {
    int e = blockIdx.x * blockDim.x + threadIdx.x;
    if (e < E) atomicAdd(&g_cnt[col[e]], 1);
}

__global__ void dinv_kernel() {
    int n = blockIdx.x * blockDim.x + threadIdx.x;
    if (n < NN) {
        int c = g_cnt[n];
        g_dinv[n] = c > 0 ? rsqrtf((float)c) : 0.0f;
    }
}

// split x into interleaved tf32 (hi, lo)
__global__ void xsplit_kernel(const float* __restrict__ x) {
    size_t i = (size_t)blockIdx.x * blockDim.x + threadIdx.x;
    if (i < (size_t)NN * 128) {
        float v = x[i];
        uint32_t hi = f2tf(v);
        g_xsplit[i] = make_uint2(hi, f2tf(v - __uint_as_float(hi)));
    }
}

__global__ void scanA_kernel() {
    __shared__ int s[SCAN_CHUNK];
    int t = threadIdx.x;
    int i = blockIdx.x * SCAN_CHUNK + t;
    s[t] = (i < NN) ? g_cnt[i] : 0;
    __syncthreads();
    for (int o = SCAN_CHUNK / 2; o > 0; o >>= 1) {
        if (t < o) s[t] += s[t + o];
        __syncthreads();
    }
    if (t == 0) g_bsum[blockIdx.x] = s[0];
}

__global__ void scanB_kernel() {
    __shared__ int s[256];
    int t = threadIdx.x;
    int val = (t < NB_SCAN) ? g_bsum[t] : 0;
    s[t] = val;
    __syncthreads();
    for (int o = 1; o < 256; o <<= 1) {
        int add = (t >= o) ? s[t - o] : 0;
        __syncthreads();
        s[t] += add;
        __syncthreads();
    }
    g_boff[t] = s[t] - val;
    if (t == NB_SCAN - 1) g_off[NN] = s[t];
}

__global__ void scanC_kernel() {
    __shared__ int s[SCAN_CHUNK];
    int t = threadIdx.x;
    int i = blockIdx.x * SCAN_CHUNK + t;
    int val = (i < NN) ? g_cnt[i] : 0;
    s[t] = val;
    __syncthreads();
    for (int o = 1; o < SCAN_CHUNK; o <<= 1) {
        int add = (t >= o) ? s[t - o] : 0;
        __syncthreads();
        s[t] += add;
        __syncthreads();
    }
    if (i < NN) {
        int excl = s[t] - val + g_boff[blockIdx.x];
        g_off[i] = excl;
        g_cur[i] = excl;
    }
}

__global__ void fill_kernel(const int* __restrict__ ei, int E) {
    int e = blockIdx.x * blockDim.x + threadIdx.x;
    if (e < E) {
        int r = ei[e];
        int c = ei[(size_t)E + e];
        float nrm = g_dinv[r] * g_dinv[c];
        int pos = atomicAdd(&g_cur[c], 1);
        g_edge[pos] = make_int2(r, __float_as_int(nrm));
    }
}

// ---------------- tensor-core GEMM (tf32 3-term) ------------------------------
// B in smem as uint2 pairs [(ks*4+c0)][g] = (W[kb+c0][g], W[kb+c0+4][g]),
// row stride GP+4 u64 (stride%16==4 -> conflict-free LDS.64).
// A: ASPLIT ? pre-split uint2 (hi,lo) LDG.64 path : fp32 + in-kernel cvt.
template <int FP, int FS, int GP, bool PERK, bool RELUIN, bool HASB,
          bool ASPLIT, int SRCSEL, int DSTSEL>
__global__ void gemm_tc(const void* __restrict__ Xext,
                        const float* __restrict__ W, int Fl, int Gl,
                        const float* __restrict__ Bias, int Bk) {
    constexpr int NCH = GP / 8;
    constexpr int KST = FP / 8;
    constexpr int BST = GP + 4;          // u64 row stride of pair arrays

    extern __shared__ unsigned char dsm_raw[];
    uint2* Wph = (uint2*)dsm_raw;                   // (FP/2)*BST u64
    uint2* Wpl = Wph + (FP / 2) * BST;
    float* Bsm = (float*)(Wpl + (FP / 2) * BST);

    const void* Xv;
    if (SRCSEL < 0) Xv = Xext;
    else if (SRCSEL == 1) Xv = (const void*)g_bufA;
    else if (SRCSEL == 3) Xv = (const void*)g_xsplit;
    else Xv = (const void*)g_hsplit;
    float* __restrict__ OUT = sel_buf(DSTSEL);

    const int kk = blockIdx.y;
    const int tid = threadIdx.x;
    const int wid = tid >> 5;
    const int lane = tid & 31;
    const int r0 = lane >> 2;    // 0..7
    const int c0 = lane & 3;     // 0..3

    // stage W as tf32 hi/lo pairs
    for (int i = tid; i < FP * GP; i += 256) {
        int f = i / GP, g = i % GP;
        float w = (f < Fl && g < Gl)
                      ? W[(size_t)kk * Fl * Gl + (size_t)f * Gl + g]
                      : 0.0f;
        uint32_t hi = f2tf(w);
        uint32_t lo = f2tf(w - __uint_as_float(hi));
        int kc = f & 7;
        int row = (f >> 3) * 4 + (kc & 3);
        int j = kc >> 2;
        ((uint32_t*)Wph)[(row * BST + g) * 2 + j] = hi;
        ((uint32_t*)Wpl)[(row * BST + g) * 2 + j] = lo;
    }
    if (tid < GP) Bsm[tid] = (HASB && tid < Gl) ? Bias[(size_t)kk * Bk + tid] : 0.0f;
    __syncthreads();

    const int mbase = blockIdx.x * 256 + wid * 32;

    const uint2* xs[4];
    const float* xf[4];
#pragma unroll
    for (int t = 0; t < 4; t++) {
        int n = mbase + t * 8 + r0;
        int nc = n < NN ? n : NN - 1;
        size_t rowoff = PERK ? ((size_t)kk * NN + nc) * FS : (size_t)nc * FS;
        if (ASPLIT) xs[t] = (const uint2*)Xv + rowoff;
        else        xf[t] = (const float*)Xv + rowoff;
    }

    float acc[2][NCH][4];
#pragma unroll
    for (int t = 0; t < 2; t++)
#pragma unroll
        for (int nc = 0; nc < NCH; nc++)
#pragma unroll
            for (int q = 0; q < 4; q++) acc[t][nc][q] = 0.0f;

#pragma unroll 2
    for (int ks = 0; ks < KST; ks++) {
        const int kb = ks * 8;
        uint32_t ahi[2][4], alo[2][4];
#pragma unroll
        for (int t = 0; t < 2; t++) {
            if (ASPLIT) {
                uint2 p;
                p = xs[2 * t + 0][kb + c0];     ahi[t][0] = p.x; alo[t][0] = p.y;
                p = xs[2 * t + 1][kb + c0];     ahi[t][1] = p.x; alo[t][1] = p.y;
                p = xs[2 * t + 0][kb + c0 + 4]; ahi[t][2] = p.x; alo[t][2] = p.y;
                p = xs[2 * t + 1][kb + c0 + 4]; ahi[t][3] = p.x; alo[t][3] = p.y;
            } else {
                float v[4];
                v[0] = xf[2 * t + 0][kb + c0];
                v[1] = xf[2 * t + 1][kb + c0];
                v[2] = xf[2 * t + 0][kb + c0 + 4];
                v[3] = xf[2 * t + 1][kb + c0 + 4];
#pragma unroll
                for (int q = 0; q < 4; q++) {
                    if (RELUIN) v[q] = fmaxf(v[q], 0.0f);
                    uint32_t hi = f2tf(v[q]);
                    ahi[t][q] = hi;
                    alo[t][q] = f2tf(v[q] - __uint_as_float(hi));
                }
            }
        }
#pragma unroll
        for (int nc = 0; nc < NCH; nc++) {
            const int bidx = (ks * 4 + c0) * BST + nc * 8 + r0;
            uint2 bh = Wph[bidx];
            uint2 bl = Wpl[bidx];
#pragma unroll
            for (int t = 0; t < 2; t++) {
                mma8(acc[t][nc], ahi[t], bh.x, bh.y);
                mma8(acc[t][nc], alo[t], bh.x, bh.y);
                mma8(acc[t][nc], ahi[t], bl.x, bl.y);
            }
        }
    }

#pragma unroll
    for (int t = 0; t < 2; t++) {
#pragma unroll
        for (int nc = 0; nc < NCH; nc++) {
            const int col = nc * 8 + 2 * c0;
            const float bx = Bsm[col], by = Bsm[col + 1];
            const int rowA = mbase + t * 16 + r0;
            const int rowB = rowA + 8;
            if (rowA < NN) {
                float2 v = make_float2(acc[t][nc][0] + bx, acc[t][nc][1] + by);
                *(float2*)(OUT + ((size_t)kk * NN + rowA) * GP + col) = v;
            }
            if (rowB < NN) {
                float2 v = make_float2(acc[t][nc][2] + bx, acc[t][nc][3] + by);
                *(float2*)(OUT + ((size_t)kk * NN + rowB) * GP + col) = v;
            }
        }
    }
}

// host-side smem bytes for an instantiation
static inline int gemm_smem_bytes(int FP, int GP) {
    return 2 * (FP / 2) * (GP + 4) * 8 + GP * 4;
}

// ---------------- CSR gather: dst[k,n] += sum_e norm_e * src[k,row_e] --------
template <int G4, int SRCSEL, int DSTSEL>
__global__ void gather_kernel() {
    const float* __restrict__ src = sel_buf(SRCSEL);
    float* __restrict__ dst = sel_buf(DSTSEL);

    constexpr int ITEMS = KK * G4;
    const long long t = blockIdx.x * (long long)blockDim.x + threadIdx.x;
    const int n = (int)(t / ITEMS);
    if (n >= NN) return;
    const int rem = (int)(t - (long long)n * ITEMS);
    const int k = rem / G4;
    const int j = rem - k * G4;

    int p = g_off[n];
    const int end = g_off[n + 1];

    const float* srcb = src + (size_t)k * NN * (G4 * 4);
    float4 acc = make_float4(0.f, 0.f, 0.f, 0.f);

    for (; p + 3 < end; p += 4) {
        int2 e0 = g_edge[p];
        int2 e1 = g_edge[p + 1];
        int2 e2 = g_edge[p + 2];
        int2 e3 = g_edge[p + 3];
        float4 v0 = *((const float4*)(srcb + (size_t)e0.x * (G4 * 4)) + j);
        float4 v1 = *((const float4*)(srcb + (size_t)e1.x * (G4 * 4)) + j);
        float4 v2 = *((const float4*)(srcb + (size_t)e2.x * (G4 * 4)) + j);
        float4 v3 = *((const float4*)(srcb + (size_t)e3.x * (G4 * 4)) + j);
        float n0 = __int_as_float(e0.y);
        float n1 = __int_as_float(e1.y);
        float n2 = __int_as_float(e2.y);
        float n3 = __int_as_float(e3.y);
        acc.x += v0.x * n0 + v1.x * n1 + v2.x * n2 + v3.x * n3;
        acc.y += v0.y * n0 + v1.y * n1 + v2.y * n2 + v3.y * n3;
        acc.z += v0.z * n0 + v1.z * n1 + v2.z * n2 + v3.z * n3;
        acc.w += v0.w * n0 + v1.w * n1 + v2.w * n2 + v3.w * n3;
    }
    for (; p < end; p++) {
        int2 e0 = g_edge[p];
        float4 v0 = *((const float4*)(srcb + (size_t)e0.x * (G4 * 4)) + j);
        float n0 = __int_as_float(e0.y);
        acc.x += v0.x * n0; acc.y += v0.y * n0;
        acc.z += v0.z * n0; acc.w += v0.w * n0;
    }

    float4* dp = (float4*)(dst + ((size_t)k * NN + n) * (G4 * 4)) + j;
    float4 cur = *dp;
    cur.x += acc.x; cur.y += acc.y; cur.z += acc.z; cur.w += acc.w;
    *dp = cur;
}

// ------- layer-1 epilogue: h = mean_k relu(bufA), emitted pre-split ----------
__global__ void combine_h_kernel() {
    int i = blockIdx.x * blockDim.x + threadIdx.x;
    if (i < NN * 64) {
        float a = g_bufA[i];
        float b = g_bufA[(size_t)NN * 64 + i];
        float v = 0.5f * (fmaxf(a, 0.f) + fmaxf(b, 0.f));
        uint32_t hi = f2tf(v);
        g_hsplit[i] = make_uint2(hi, f2tf(v - __uint_as_float(hi)));
    }
}

// ---------------- final: mean_k relu + log_softmax (C=41, stride 48) ---------
__global__ void final_kernel(float* __restrict__ out) {
    const int warp = (int)((blockIdx.x * (size_t)blockDim.x + threadIdx.x) >> 5);
    const int lane = threadIdx.x & 31;
    if (warp >= NN) return;

    const size_t b0 = (size_t)warp * 48;
    const size_t b1 = ((size_t)NN + warp) * 48;

    float v1 = -1e30f, v2 = -1e30f;
    if (lane < 41)
        v1 = 0.5f * (fmaxf(g_bufA[b0 + lane], 0.f) + fmaxf(g_bufA[b1 + lane], 0.f));
    if (lane + 32 < 41)
        v2 = 0.5f * (fmaxf(g_bufA[b0 + lane + 32], 0.f) + fmaxf(g_bufA[b1 + lane + 32], 0.f));

    float m = fmaxf(v1, v2);
#pragma unroll
    for (int o = 16; o; o >>= 1) m = fmaxf(m, __shfl_xor_sync(0xFFFFFFFFu, m, o));

    float s = 0.f;
    if (lane < 41) s += expf(v1 - m);
    if (lane + 32 < 41) s += expf(v2 - m);
#pragma unroll
    for (int o = 16; o; o >>= 1) s += __shfl_xor_sync(0xFFFFFFFFu, s, o);

    const float l = m + logf(s);
    if (lane < 41) out[(size_t)warp * 41 + lane] = v1 - l;
    if (lane + 32 < 41) out[(size_t)warp * 41 + lane + 32] = v2 - l;
}

// ---------------- host driver ------------------------------------------------
extern "C" void kernel_launch(void* const* d_in, const int* in_sizes, int n_in,
                              void* d_out, int out_size) {
    const float* x       = (const float*)d_in[0];
    const int*   ei      = (const int*)d_in[1];   // int32 (JAX x64 disabled)
    const float* w1_init = (const float*)d_in[2];
    const float* w1_mid  = (const float*)d_in[3];  // [1,K,64,64]
    const float* w1_root = (const float*)d_in[4];  // [2,K,128,64]
    const float* b1      = (const float*)d_in[5];  // [2,K,1,64]
    const float* w2_init = (const float*)d_in[6];
    const float* w2_mid  = (const float*)d_in[7];  // [1,K,41,41]
    const float* w2_root = (const float*)d_in[8];  // [2,K,64,41]
    const float* b2      = (const float*)d_in[9];  // [2,K,1,41]
    float* out = (float*)d_out;
    const int E = in_sizes[1] / 2;

    const int nb_n  = (NN + 255) / 256;
    const int nb_e  = (E + 255) / 256;
    const int nb_xs = (int)(((size_t)NN * 128 + 255) / 256);
    const int nb_g1 = (int)(((long long)NN * 32 + 255) / 256);  // G4=16
    const int nb_g2 = (int)(((long long)NN * 24 + 255) / 256);  // G4=12

    const dim3 g_tc((NN + 255) / 256, KK);

    const int sm_128_64 = gemm_smem_bytes(128, 64);  // 69,888 > 48KB: opt-in
    const int sm_64_64  = gemm_smem_bytes(64, 64);
    const int sm_64_48  = gemm_smem_bytes(64, 48);
    const int sm_48_48  = gemm_smem_bytes(48, 48);

    cudaFuncSetAttribute(
        gemm_tc<128, 128, 64, false, false, false, true, 3, 0>,
        cudaFuncAttributeMaxDynamicSharedMemorySize, sm_128_64);
    cudaFuncSetAttribute(
        gemm_tc<128, 128, 64, false, false, true, true, 3, 1>,
        cudaFuncAttributeMaxDynamicSharedMemorySize, sm_128_64);

    // prep + split, big GEMMs early, then CSR build
    zero_cnt_kernel<<<nb_n, 256>>>();
    count_kernel<<<nb_e, 256>>>(ei + E, E);
    xsplit_kernel<<<nb_xs, 256>>>(x);
    dinv_kernel<<<nb_n, 256>>>();
    gemm_tc<128, 128, 64, false, false, false, true, 3, 0>
        <<<g_tc, 256, sm_128_64>>>(nullptr, w1_init, 128, 64, nullptr, 0);
    gemm_tc<128, 128, 64, false, false, true, true, 3, 1>
        <<<g_tc, 256, sm_128_64>>>(nullptr, w1_root, 128, 64, b1, 64);
    scanA_kernel<<<NB_SCAN, SCAN_CHUNK>>>();
    scanB_kernel<<<1, 256>>>();
    scanC_kernel<<<NB_SCAN, SCAN_CHUNK>>>();
    fill_kernel<<<nb_e, 256>>>(ei, E);

    // ================= layer 1 (Fin=128 -> H=64, stride 64) =================
    gather_kernel<16, 0, 1><<<nb_g1, 256>>>();
    gemm_tc<64, 64, 64, true, true, false, false, 1, 0><<<g_tc, 256, sm_64_64>>>(
        nullptr, w1_mid, 64, 64, nullptr, 0);
    gemm_tc<128, 128, 64, false, false, true, true, 3, 1>
        <<<g_tc, 256, sm_128_64>>>(nullptr, w1_root + (size_t)2 * 128 * 64,
                                   128, 64, b1 + 2 * 64, 64);
    gather_kernel<16, 0, 1><<<nb_g1, 256>>>();
    combine_h_kernel<<<(NN * 64 + 255) / 256, 256>>>();

    // ================= layer 2 (H=64 -> C=41, stride 48) ====================
    gemm_tc<64, 64, 48, false, false, false, true, 4, 0><<<g_tc, 256, sm_64_48>>>(
        nullptr, w2_init, 64, 41, nullptr, 0);
    gemm_tc<64, 64, 48, false, false, true, true, 4, 1><<<g_tc, 256, sm_64_48>>>(
        nullptr, w2_root, 64, 41, b2, 41);
    gather_kernel<12, 0, 1><<<nb_g2, 256>>>();
    gemm_tc<48, 48, 48, true, true, false, false, 1, 0><<<g_tc, 256, sm_48_48>>>(
        nullptr, w2_mid, 41, 41, nullptr, 0);
    gemm_tc<64, 64, 48, false, false, true, true, 4, 1><<<g_tc, 256, sm_64_48>>>(
        nullptr, w2_root + (size_t)2 * 64 * 41, 64, 41, b2 + 2 * 41, 41);
    gather_kernel<12, 0, 1><<<nb_g2, 256>>>();

    // mean over k + log_softmax
    final_kernel<<<(NN * 32 + 255) / 256, 256>>>(out);
}

// round 11
// speedup vs baseline: 1.1406x; 1.1406x over previous
#include <cuda_runtime.h>
#include <cstdint>

#define NN 100000
#define KK 2
#define EMAX 1600000
#define SCAN_CHUNK 512
#define NB_SCAN ((NN + SCAN_CHUNK - 1) / SCAN_CHUNK)   // 196

// ---------------- scratch (static device globals; no allocation) -------------
__device__ float g_dinv[NN];
__device__ int   g_cnt[NN];
__device__ int   g_off[NN + 1];
__device__ int   g_cur[NN];
__device__ int   g_bsum[256];
__device__ int   g_boff[256];
__device__ int2  g_edge[EMAX];                       // (row, norm), CSR by col
__device__ float g_bufT[(size_t)KK * NN * 64 + 64];  // 51.2 MB
__device__ float g_bufA[(size_t)KK * NN * 64 + 64];  // 51.2 MB
__device__ float g_h[(size_t)NN * 64 + 64];          // 25.6 MB

__device__ __forceinline__ float* sel_buf(int s) {
    return s == 0 ? g_bufT : (s == 1 ? g_bufA : g_h);
}

// ---------------- tf32 helpers -----------------------------------------------
__device__ __forceinline__ uint32_t f2tf(float f) {
    uint32_t r;
    asm("cvt.rna.tf32.f32 %0, %1;" : "=r"(r) : "f"(f));
    return r;
}

__device__ __forceinline__ void mma8(float* d, const uint32_t* a,
                                     uint32_t b0, uint32_t b1) {
    asm("mma.sync.aligned.m16n8k8.row.col.f32.tf32.tf32.f32 "
        "{%0,%1,%2,%3}, {%4,%5,%6,%7}, {%8,%9}, {%0,%1,%2,%3};"
        : "+f"(d[0]), "+f"(d[1]), "+f"(d[2]), "+f"(d[3])
        : "r"(a[0]), "r"(a[1]), "r"(a[2]), "r"(a[3]), "r"(b0), "r"(b1));
}

// ---------------- prep: degree, CSR build ------------------------------------
__global__ void zero_cnt_kernel() {
    int n = blockIdx.x * blockDim.x + threadIdx.x;
    if (n < NN) g_cnt[n] = 0;
}

__global__ void count_kernel(const int* __restrict__ col, int E) {
    int e = blockIdx.x * blockDim.x + threadIdx.x;
    if (e < E) atomicAdd(&g_cnt[col[e]], 1);
}

__global__ void dinv_kernel() {
    int n = blockIdx.x * blockDim.x + threadIdx.x;
    if (n < NN) {
        int c = g_cnt[n];
        g_dinv[n] = c > 0 ? rsqrtf((float)c) : 0.0f;
    }
}

__global__ void scanA_kernel() {
    __shared__ int s[SCAN_CHUNK];
    int t = threadIdx.x;
    int i = blockIdx.x * SCAN_CHUNK + t;
    s[t] = (i < NN) ? g_cnt[i] : 0;
    __syncthreads();
    for (int o = SCAN_CHUNK / 2; o > 0; o >>= 1) {
        if (t < o) s[t] += s[t + o];
        __syncthreads();
    }
    if (t == 0) g_bsum[blockIdx.x] = s[0];
}

__global__ void scanB_kernel() {
    __shared__ int s[256];
    int t = threadIdx.x;
    int val = (t < NB_SCAN) ? g_bsum[t] : 0;
    s[t] = val;
    __syncthreads();
    for (int o = 1; o < 256; o <<= 1) {
        int add = (t >= o) ? s[t - o] : 0;
        __syncthreads();
        s[t] += add;
        __syncthreads();
    }
    g_boff[t] = s[t] - val;
    if (t == NB_SCAN - 1) g_off[NN] = s[t];
}

__global__ void scanC_kernel() {
    __shared__ int s[SCAN_CHUNK];
    int t = threadIdx.x;
    int i = blockIdx.x * SCAN_CHUNK + t;
    int val = (i < NN) ? g_cnt[i] : 0;
    s[t] = val;
    __syncthreads();
    for (int o = 1; o < SCAN_CHUNK; o <<= 1) {
        int add = (t >= o) ? s[t - o] : 0;
        __syncthreads();
        s[t] += add;
        __syncthreads();
    }
    if (i < NN) {
        int excl = s[t] - val + g_boff[blockIdx.x];
        g_off[i] = excl;
        g_cur[i] = excl;
    }
}

__global__ void fill_kernel(const int* __restrict__ ei, int E) {
    int e = blockIdx.x * blockDim.x + threadIdx.x;
    if (e < E) {
        int r = ei[e];
        int c = ei[(size_t)E + e];
        float nrm = g_dinv[r] * g_dinv[c];
        int pos = atomicAdd(&g_cur[c], 1);
        g_edge[pos] = make_int2(r, __float_as_int(nrm));
    }
}

// ---------------- tensor-core GEMM (tf32 3-term, paired-B LDS.64) ------------
// OUT[k, n, 0:GP] = X[(k,)n, 0:FP] @ W (+ bias).  256 thr = 8 warps; warp does
// 32 rows x GP cols via m16n8k8.  W staged once as tf32 hi/lo uint2 PAIRS
// [(ks*4+c0)][g] = (W[kb+c0][g], W[kb+c0+4][g]) with u64 row stride GP+4
// (stride%16==4 -> both half-warps hit 16 distinct u64 banks; conflict-free).
// A: fp32 loads + in-kernel hi/lo split (cheap, no extra DRAM traffic).
template <int FP, int FS, int GP, bool PERK, bool RELUIN, bool HASB,
          int SRCSEL, int DSTSEL>
__global__ void gemm_tc(const float* __restrict__ Xext,
                        const float* __restrict__ W, int Fl, int Gl,
                        const float* __restrict__ Bias, int Bk) {
    constexpr int NCH = GP / 8;
    constexpr int KST = FP / 8;
    constexpr int BST = GP + 4;          // u64 row stride of pair arrays

    extern __shared__ unsigned char dsm_raw[];
    uint2* Wph = (uint2*)dsm_raw;                   // (FP/2)*BST u64 pairs
    uint2* Wpl = Wph + (FP / 2) * BST;
    float* Bsm = (float*)(Wpl + (FP / 2) * BST);

    const float* __restrict__ X = (SRCSEL < 0) ? Xext : sel_buf(SRCSEL);
    float* __restrict__ OUT = sel_buf(DSTSEL);

    const int kk = blockIdx.y;
    const int tid = threadIdx.x;
    const int wid = tid >> 5;
    const int lane = tid & 31;
    const int r0 = lane >> 2;    // 0..7
    const int c0 = lane & 3;     // 0..3

    // stage W as tf32 hi/lo pairs: row = (f/8)*4 + (f%4), j = (f%8)/4
    for (int i = tid; i < FP * GP; i += 256) {
        int f = i / GP, g = i % GP;
        float w = (f < Fl && g < Gl)
                      ? W[(size_t)kk * Fl * Gl + (size_t)f * Gl + g]
                      : 0.0f;
        uint32_t hi = f2tf(w);
        uint32_t lo = f2tf(w - __uint_as_float(hi));
        int kc = f & 7;
        int row = (f >> 3) * 4 + (kc & 3);
        int j = kc >> 2;
        ((uint32_t*)Wph)[(row * BST + g) * 2 + j] = hi;
        ((uint32_t*)Wpl)[(row * BST + g) * 2 + j] = lo;
    }
    if (tid < GP) Bsm[tid] = (HASB && tid < Gl) ? Bias[(size_t)kk * Bk + tid] : 0.0f;
    __syncthreads();

    const int mbase = blockIdx.x * 256 + wid * 32;

    // 4 row groups: r0, r0+8 (tile 0), r0+16, r0+24 (tile 1); clamp loads.
    const float* xp[4];
#pragma unroll
    for (int t = 0; t < 4; t++) {
        int n = mbase + t * 8 + r0;
        int nc = n < NN ? n : NN - 1;
        xp[t] = X + (PERK ? ((size_t)kk * NN + nc) * FS : (size_t)nc * FS);
    }

    float acc[2][NCH][4];
#pragma unroll
    for (int t = 0; t < 2; t++)
#pragma unroll
        for (int nc = 0; nc < NCH; nc++)
#pragma unroll
            for (int q = 0; q < 4; q++) acc[t][nc][q] = 0.0f;

#pragma unroll 2
    for (int ks = 0; ks < KST; ks++) {
        const int kb = ks * 8;
        uint32_t ahi[2][4], alo[2][4];
#pragma unroll
        for (int t = 0; t < 2; t++) {
            float v[4];
            v[0] = xp[2 * t + 0][kb + c0];
            v[1] = xp[2 * t + 1][kb + c0];
            v[2] = xp[2 * t + 0][kb + c0 + 4];
            v[3] = xp[2 * t + 1][kb + c0 + 4];
#pragma unroll
            for (int q = 0; q < 4; q++) {
                if (RELUIN) v[q] = fmaxf(v[q], 0.0f);
                uint32_t hi = f2tf(v[q]);
                ahi[t][q] = hi;
                alo[t][q] = f2tf(v[q] - __uint_as_float(hi));
            }
        }
#pragma unroll
        for (int nc = 0; nc < NCH; nc++) {
            const int bidx = (ks * 4 + c0) * BST + nc * 8 + r0;
            uint2 bh = Wph[bidx];
            uint2 bl = Wpl[bidx];
#pragma unroll
            for (int t = 0; t < 2; t++) {
                mma8(acc[t][nc], ahi[t], bh.x, bh.y);
                mma8(acc[t][nc], alo[t], bh.x, bh.y);
                mma8(acc[t][nc], ahi[t], bl.x, bl.y);
            }
        }
    }

#pragma unroll
    for (int t = 0; t < 2; t++) {
#pragma unroll
        for (int nc = 0; nc < NCH; nc++) {
            const int col = nc * 8 + 2 * c0;
            const float bx = Bsm[col], by = Bsm[col + 1];
            const int rowA = mbase + t * 16 + r0;
            const int rowB = rowA + 8;
            if (rowA < NN) {
                float2 v = make_float2(acc[t][nc][0] + bx, acc[t][nc][1] + by);
                *(float2*)(OUT + ((size_t)kk * NN + rowA) * GP + col) = v;
            }
            if (rowB < NN) {
                float2 v = make_float2(acc[t][nc][2] + bx, acc[t][nc][3] + by);
                *(float2*)(OUT + ((size_t)kk * NN + rowB) * GP + col) = v;
            }
        }
    }
}

// host-side smem bytes for an instantiation
static inline int gemm_smem_bytes(int FP, int GP) {
    return 2 * (FP / 2) * (GP + 4) * 8 + GP * 4;
}

// ---------------- CSR gather: dst[k,n] += sum_e norm_e * src[k,row_e] --------
// Flat mapping: item t -> (n, k, j).  Unroll-4 for MLP depth.
template <int G4, int SRCSEL, int DSTSEL>
__global__ void gather_kernel() {
    const float* __restrict__ src = sel_buf(SRCSEL);
    float* __restrict__ dst = sel_buf(DSTSEL);

    constexpr int ITEMS = KK * G4;
    const long long t = blockIdx.x * (long long)blockDim.x + threadIdx.x;
    const int n = (int)(t / ITEMS);
    if (n >= NN) return;
    const int rem = (int)(t - (long long)n * ITEMS);
    const int k = rem / G4;
    const int j = rem - k * G4;

    int p = g_off[n];
    const int end = g_off[n + 1];

    const float* srcb = src + (size_t)k * NN * (G4 * 4);
    float4 acc = make_float4(0.f, 0.f, 0.f, 0.f);

    for (; p + 3 < end; p += 4) {
        int2 e0 = g_edge[p];
        int2 e1 = g_edge[p + 1];
        int2 e2 = g_edge[p + 2];
        int2 e3 = g_edge[p + 3];
        float4 v0 = *((const float4*)(srcb + (size_t)e0.x * (G4 * 4)) + j);
        float4 v1 = *((const float4*)(srcb + (size_t)e1.x * (G4 * 4)) + j);
        float4 v2 = *((const float4*)(srcb + (size_t)e2.x * (G4 * 4)) + j);
        float4 v3 = *((const float4*)(srcb + (size_t)e3.x * (G4 * 4)) + j);
        float n0 = __int_as_float(e0.y);
        float n1 = __int_as_float(e1.y);
        float n2 = __int_as_float(e2.y);
        float n3 = __int_as_float(e3.y);
        acc.x += v0.x * n0 + v1.x * n1 + v2.x * n2 + v3.x * n3;
        acc.y += v0.y * n0 + v1.y * n1 + v2.y * n2 + v3.y * n3;
        acc.z += v0.z * n0 + v1.z * n1 + v2.z * n2 + v3.z * n3;
        acc.w += v0.w * n0 + v1.w * n1 + v2.w * n2 + v3.w * n3;
    }
    for (; p < end; p++) {
        int2 e0 = g_edge[p];
        float4 v0 = *((const float4*)(srcb + (size_t)e0.x * (G4 * 4)) + j);
        float n0 = __int_as_float(e0.y);
        acc.x += v0.x * n0; acc.y += v0.y * n0;
        acc.z += v0.z * n0; acc.w += v0.w * n0;
    }

    float4* dp = (float4*)(dst + ((size_t)k * NN + n) * (G4 * 4)) + j;
    float4 cur = *dp;
    cur.x += acc.x; cur.y += acc.y; cur.z += acc.z; cur.w += acc.w;
    *dp = cur;
}

// ---------------- layer-1 epilogue: h = mean_k relu(bufA) (stride 64) --------
__global__ void combine_h_kernel() {
    int i = blockIdx.x * blockDim.x + threadIdx.x;
    if (i < NN * 64) {
        float a = g_bufA[i];
        float b = g_bufA[(size_t)NN * 64 + i];
        g_h[i] = 0.5f * (fmaxf(a, 0.f) + fmaxf(b, 0.f));
    }
}

// ---------------- final: mean_k relu + log_softmax (C=41, stride 48) ---------
__global__ void final_kernel(float* __restrict__ out) {
    const int warp = (int)((blockIdx.x * (size_t)blockDim.x + threadIdx.x) >> 5);
    const int lane = threadIdx.x & 31;
    if (warp >= NN) return;

    const size_t b0 = (size_t)warp * 48;
    const size_t b1 = ((size_t)NN + warp) * 48;

    float v1 = -1e30f, v2 = -1e30f;
    if (lane < 41)
        v1 = 0.5f * (fmaxf(g_bufA[b0 + lane], 0.f) + fmaxf(g_bufA[b1 + lane], 0.f));
    if (lane + 32 < 41)
        v2 = 0.5f * (fmaxf(g_bufA[b0 + lane + 32], 0.f) + fmaxf(g_bufA[b1 + lane + 32], 0.f));

    float m = fmaxf(v1, v2);
#pragma unroll
    for (int o = 16; o; o >>= 1) m = fmaxf(m, __shfl_xor_sync(0xFFFFFFFFu, m, o));

    float s = 0.f;
    if (lane < 41) s += expf(v1 - m);
    if (lane + 32 < 41) s += expf(v2 - m);
#pragma unroll
    for (int o = 16; o; o >>= 1) s += __shfl_xor_sync(0xFFFFFFFFu, s, o);

    const float l = m + logf(s);
    if (lane < 41) out[(size_t)warp * 41 + lane] = v1 - l;
    if (lane + 32 < 41) out[(size_t)warp * 41 + lane + 32] = v2 - l;
}

// ---------------- host driver ------------------------------------------------
extern "C" void kernel_launch(void* const* d_in, const int* in_sizes, int n_in,
                              void* d_out, int out_size) {
    const float* x       = (const float*)d_in[0];
    const int*   ei      = (const int*)d_in[1];   // int32 (JAX x64 disabled)
    const float* w1_init = (const float*)d_in[2];
    const float* w1_mid  = (const float*)d_in[3];  // [1,K,64,64]
    const float* w1_root = (const float*)d_in[4];  // [2,K,128,64]
    const float* b1      = (const float*)d_in[5];  // [2,K,1,64]
    const float* w2_init = (const float*)d_in[6];
    const float* w2_mid  = (const float*)d_in[7];  // [1,K,41,41]
    const float* w2_root = (const float*)d_in[8];  // [2,K,64,41]
    const float* b2      = (const float*)d_in[9];  // [2,K,1,41]
    float* out = (float*)d_out;
    const int E = in_sizes[1] / 2;

    const int nb_n  = (NN + 255) / 256;
    const int nb_e  = (E + 255) / 256;
    const int nb_g1 = (int)(((long long)NN * 32 + 255) / 256);  // G4=16
    const int nb_g2 = (int)(((long long)NN * 24 + 255) / 256);  // G4=12

    const dim3 g_tc((NN + 255) / 256, KK);

    const int sm_128_64 = gemm_smem_bytes(128, 64);  // 69,888 > 48KB: opt-in
    const int sm_64_64  = gemm_smem_bytes(64, 64);
    const int sm_64_48  = gemm_smem_bytes(64, 48);
    const int sm_48_48  = gemm_smem_bytes(48, 48);

    cudaFuncSetAttribute(gemm_tc<128, 128, 64, false, false, false, -1, 0>,
                         cudaFuncAttributeMaxDynamicSharedMemorySize, sm_128_64);
    cudaFuncSetAttribute(gemm_tc<128, 128, 64, false, false, true, -1, 1>,
                         cudaFuncAttributeMaxDynamicSharedMemorySize, sm_128_64);

    // prep head, big layer-1 GEMMs early (ncu window), rest of CSR build.
    zero_cnt_kernel<<<nb_n, 256>>>();
    count_kernel<<<nb_e, 256>>>(ei + E, E);
    dinv_kernel<<<nb_n, 256>>>();
    gemm_tc<128, 128, 64, false, false, false, -1, 0>
        <<<g_tc, 256, sm_128_64>>>(x, w1_init, 128, 64, nullptr, 0);
    gemm_tc<128, 128, 64, false, false, true, -1, 1>
        <<<g_tc, 256, sm_128_64>>>(x, w1_root, 128, 64, b1, 64);
    scanA_kernel<<<NB_SCAN, SCAN_CHUNK>>>();
    scanB_kernel<<<1, 256>>>();
    scanC_kernel<<<NB_SCAN, SCAN_CHUNK>>>();
    fill_kernel<<<nb_e, 256>>>(ei, E);

    // ================= layer 1 (Fin=128 -> H=64, stride 64) =================
    gather_kernel<16, 0, 1><<<nb_g1, 256>>>();
    gemm_tc<64, 64, 64, true, true, false, 1, 0><<<g_tc, 256, sm_64_64>>>(
        nullptr, w1_mid, 64, 64, nullptr, 0);
    gemm_tc<128, 128, 64, false, false, true, -1, 1>
        <<<g_tc, 256, sm_128_64>>>(x, w1_root + (size_t)2 * 128 * 64, 128, 64,
                                   b1 + 2 * 64, 64);
    gather_kernel<16, 0, 1><<<nb_g1, 256>>>();
    combine_h_kernel<<<(NN * 64 + 255) / 256, 256>>>();

    // ================= layer 2 (H=64 -> C=41, stride 48) ====================
    gemm_tc<64, 64, 48, false, false, false, 2, 0><<<g_tc, 256, sm_64_48>>>(
        nullptr, w2_init, 64, 41, nullptr, 0);
    gemm_tc<64, 64, 48, false, false, true, 2, 1><<<g_tc, 256, sm_64_48>>>(
        nullptr, w2_root, 64, 41, b2, 41);
    gather_kernel<12, 0, 1><<<nb_g2, 256>>>();
    gemm_tc<48, 48, 48, true, true, false, 1, 0><<<g_tc, 256, sm_48_48>>>(
        nullptr, w2_mid, 41, 41, nullptr, 0);
    gemm_tc<64, 64, 48, false, false, true, 2, 1><<<g_tc, 256, sm_64_48>>>(
        nullptr, w2_root + (size_t)2 * 64 * 41, 64, 41, b2 + 2 * 41, 41);
    gather_kernel<12, 0, 1><<<nb_g2, 256>>>();

    // mean over k + log_softmax
    final_kernel<<<(NN * 32 + 255) / 256, 256>>>(out);
}

// round 12
// speedup vs baseline: 1.2444x; 1.0910x over previous
#include <cuda_runtime.h>
#include <cstdint>

#define NN 100000
#define KK 2
#define EMAX 1600000
#define SCAN_CHUNK 512
#define NB_SCAN ((NN + SCAN_CHUNK - 1) / SCAN_CHUNK)   // 196

// ---------------- scratch (static device globals; no allocation) -------------
__device__ float g_dinv[NN];
__device__ int   g_cnt[NN];
__device__ int   g_off[NN + 1];
__device__ int   g_cur[NN];
__device__ int   g_bsum[256];
__device__ int   g_boff[256];
__device__ int2  g_edge[EMAX];                       // (row, norm), CSR by col
__device__ float g_bufT[(size_t)KK * NN * 64 + 64];  // 51.2 MB
__device__ float g_bufA[(size_t)KK * NN * 64 + 64];  // 51.2 MB
__device__ float g_h[(size_t)NN * 64 + 64];          // 25.6 MB
__device__ float g_bufC[(size_t)KK * NN * 64 + 64];  // 51.2 MB (breaks WAR)

__device__ __forceinline__ float* sel_buf(int s) {
    return s == 0 ? g_bufT : (s == 1 ? g_bufA : (s == 2 ? g_h : g_bufC));
}

// ---------------- tf32 helpers -----------------------------------------------
__device__ __forceinline__ uint32_t f2tf(float f) {
    uint32_t r;
    asm("cvt.rna.tf32.f32 %0, %1;" : "=r"(r) : "f"(f));
    return r;
}

__device__ __forceinline__ void mma8(float* d, const uint32_t* a,
                                     uint32_t b0, uint32_t b1) {
    asm("mma.sync.aligned.m16n8k8.row.col.f32.tf32.tf32.f32 "
        "{%0,%1,%2,%3}, {%4,%5,%6,%7}, {%8,%9}, {%0,%1,%2,%3};"
        : "+f"(d[0]), "+f"(d[1]), "+f"(d[2]), "+f"(d[3])
        : "r"(a[0]), "r"(a[1]), "r"(a[2]), "r"(a[3]), "r"(b0), "r"(b1));
}

// ---------------- prep: degree, CSR build ------------------------------------
__global__ void zero_cnt_kernel() {
    int n = blockIdx.x * blockDim.x + threadIdx.x;
    if (n < NN) g_cnt[n] = 0;
}

__global__ void count_kernel(const int* __restrict__ col, int E) {
    int e = blockIdx.x * blockDim.x + threadIdx.x;
    if (e < E) atomicAdd(&g_cnt[col[e]], 1);
}

__global__ void dinv_kernel() {
    int n = blockIdx.x * blockDim.x + threadIdx.x;
    if (n < NN) {
        int c = g_cnt[n];
        g_dinv[n] = c > 0 ? rsqrtf((float)c) : 0.0f;
    }
}

__global__ void scanA_kernel() {
    __shared__ int s[SCAN_CHUNK];
    int t = threadIdx.x;
    int i = blockIdx.x * SCAN_CHUNK + t;
    s[t] = (i < NN) ? g_cnt[i] : 0;
    __syncthreads();
    for (int o = SCAN_CHUNK / 2; o > 0; o >>= 1) {
        if (t < o) s[t] += s[t + o];
        __syncthreads();
    }
    if (t == 0) g_bsum[blockIdx.x] = s[0];
}

__global__ void scanB_kernel() {
    __shared__ int s[256];
    int t = threadIdx.x;
    int val = (t < NB_SCAN) ? g_bsum[t] : 0;
    s[t] = val;
    __syncthreads();
    for (int o = 1; o < 256; o <<= 1) {
        int add = (t >= o) ? s[t - o] : 0;
        __syncthreads();
        s[t] += add;
        __syncthreads();
    }
    g_boff[t] = s[t] - val;
    if (t == NB_SCAN - 1) g_off[NN] = s[t];
}

__global__ void scanC_kernel() {
    __shared__ int s[SCAN_CHUNK];
    int t = threadIdx.x;
    int i = blockIdx.x * SCAN_CHUNK + t;
    int val = (i < NN) ? g_cnt[i] : 0;
    s[t] = val;
    __syncthreads();
    for (int o = 1; o < SCAN_CHUNK; o <<= 1) {
        int add = (t >= o) ? s[t - o] : 0;
        __syncthreads();
        s[t] += add;
        __syncthreads();
    }
    if (i < NN) {
        int excl = s[t] - val + g_boff[blockIdx.x];
        g_off[i] = excl;
        g_cur[i] = excl;
    }
}

__global__ void fill_kernel(const int* __restrict__ ei, int E) {
    int e = blockIdx.x * blockDim.x + threadIdx.x;
    if (e < E) {
        int r = ei[e];
        int c = ei[(size_t)E + e];
        float nrm = g_dinv[r] * g_dinv[c];
        int pos = atomicAdd(&g_cur[c], 1);
        g_edge[pos] = make_int2(r, __float_as_int(nrm));
    }
}

// ---------------- tensor-core GEMM (tf32 3-term, paired-B LDS.64) ------------
template <int FP, int FS, int GP, bool PERK, bool RELUIN, bool HASB,
          int SRCSEL, int DSTSEL>
__global__ void gemm_tc(const float* __restrict__ Xext,
                        const float* __restrict__ W, int Fl, int Gl,
                        const float* __restrict__ Bias, int Bk) {
    constexpr int NCH = GP / 8;
    constexpr int KST = FP / 8;
    constexpr int BST = GP + 4;          // u64 row stride of pair arrays

    extern __shared__ unsigned char dsm_raw[];
    uint2* Wph = (uint2*)dsm_raw;                   // (FP/2)*BST u64 pairs
    uint2* Wpl = Wph + (FP / 2) * BST;
    float* Bsm = (float*)(Wpl + (FP / 2) * BST);

    const float* __restrict__ X = (SRCSEL < 0) ? Xext : sel_buf(SRCSEL);
    float* __restrict__ OUT = sel_buf(DSTSEL);

    const int kk = blockIdx.y;
    const int tid = threadIdx.x;
    const int wid = tid >> 5;
    const int lane = tid & 31;
    const int r0 = lane >> 2;    // 0..7
    const int c0 = lane & 3;     // 0..3

    for (int i = tid; i < FP * GP; i += 256) {
        int f = i / GP, g = i % GP;
        float w = (f < Fl && g < Gl)
                      ? W[(size_t)kk * Fl * Gl + (size_t)f * Gl + g]
                      : 0.0f;
        uint32_t hi = f2tf(w);
        uint32_t lo = f2tf(w - __uint_as_float(hi));
        int kc = f & 7;
        int row = (f >> 3) * 4 + (kc & 3);
        int j = kc >> 2;
        ((uint32_t*)Wph)[(row * BST + g) * 2 + j] = hi;
        ((uint32_t*)Wpl)[(row * BST + g) * 2 + j] = lo;
    }
    if (tid < GP) Bsm[tid] = (HASB && tid < Gl) ? Bias[(size_t)kk * Bk + tid] : 0.0f;
    __syncthreads();

    const int mbase = blockIdx.x * 256 + wid * 32;

    const float* xp[4];
#pragma unroll
    for (int t = 0; t < 4; t++) {
        int n = mbase + t * 8 + r0;
        int nc = n < NN ? n : NN - 1;
        xp[t] = X + (PERK ? ((size_t)kk * NN + nc) * FS : (size_t)nc * FS);
    }

    float acc[2][NCH][4];
#pragma unroll
    for (int t = 0; t < 2; t++)
#pragma unroll
        for (int nc = 0; nc < NCH; nc++)
#pragma unroll
            for (int q = 0; q < 4; q++) acc[t][nc][q] = 0.0f;

#pragma unroll 2
    for (int ks = 0; ks < KST; ks++) {
        const int kb = ks * 8;
        uint32_t ahi[2][4], alo[2][4];
#pragma unroll
        for (int t = 0; t < 2; t++) {
            float v[4];
            v[0] = xp[2 * t + 0][kb + c0];
            v[1] = xp[2 * t + 1][kb + c0];
            v[2] = xp[2 * t + 0][kb + c0 + 4];
            v[3] = xp[2 * t + 1][kb + c0 + 4];
#pragma unroll
            for (int q = 0; q < 4; q++) {
                if (RELUIN) v[q] = fmaxf(v[q], 0.0f);
                uint32_t hi = f2tf(v[q]);
                ahi[t][q] = hi;
                alo[t][q] = f2tf(v[q] - __uint_as_float(hi));
            }
        }
#pragma unroll
        for (int nc = 0; nc < NCH; nc++) {
            const int bidx = (ks * 4 + c0) * BST + nc * 8 + r0;
            uint2 bh = Wph[bidx];
            uint2 bl = Wpl[bidx];
#pragma unroll
            for (int t = 0; t < 2; t++) {
                mma8(acc[t][nc], ahi[t], bh.x, bh.y);
                mma8(acc[t][nc], alo[t], bh.x, bh.y);
                mma8(acc[t][nc], ahi[t], bl.x, bl.y);
            }
        }
    }

#pragma unroll
    for (int t = 0; t < 2; t++) {
#pragma unroll
        for (int nc = 0; nc < NCH; nc++) {
            const int col = nc * 8 + 2 * c0;
            const float bx = Bsm[col], by = Bsm[col + 1];
            const int rowA = mbase + t * 16 + r0;
            const int rowB = rowA + 8;
            if (rowA < NN) {
                float2 v = make_float2(acc[t][nc][0] + bx, acc[t][nc][1] + by);
                *(float2*)(OUT + ((size_t)kk * NN + rowA) * GP + col) = v;
            }
            if (rowB < NN) {
                float2 v = make_float2(acc[t][nc][2] + bx, acc[t][nc][3] + by);
                *(float2*)(OUT + ((size_t)kk * NN + rowB) * GP + col) = v;
            }
        }
    }
}

static inline int gemm_smem_bytes(int FP, int GP) {
    return 2 * (FP / 2) * (GP + 4) * 8 + GP * 4;
}

// ---------------- CSR gather: dst[k,n] += sum_e norm_e * src[k,row_e] --------
template <int G4, int SRCSEL, int DSTSEL>
__global__ void gather_kernel() {
    const float* __restrict__ src = sel_buf(SRCSEL);
    float* __restrict__ dst = sel_buf(DSTSEL);

    constexpr int ITEMS = KK * G4;
    const long long t = blockIdx.x * (long long)blockDim.x + threadIdx.x;
    const int n = (int)(t / ITEMS);
    if (n >= NN) return;
    const int rem = (int)(t - (long long)n * ITEMS);
    const int k = rem / G4;
    const int j = rem - k * G4;

    int p = g_off[n];
    const int end = g_off[n + 1];

    const float* srcb = src + (size_t)k * NN * (G4 * 4);
    float4 acc = make_float4(0.f, 0.f, 0.f, 0.f);

    for (; p + 3 < end; p += 4) {
        int2 e0 = g_edge[p];
        int2 e1 = g_edge[p + 1];
        int2 e2 = g_edge[p + 2];
        int2 e3 = g_edge[p + 3];
        float4 v0 = *((const float4*)(srcb + (size_t)e0.x * (G4 * 4)) + j);
        float4 v1 = *((const float4*)(srcb + (size_t)e1.x * (G4 * 4)) + j);
        float4 v2 = *((const float4*)(srcb + (size_t)e2.x * (G4 * 4)) + j);
        float4 v3 = *((const float4*)(srcb + (size_t)e3.x * (G4 * 4)) + j);
        float n0 = __int_as_float(e0.y);
        float n1 = __int_as_float(e1.y);
        float n2 = __int_as_float(e2.y);
        float n3 = __int_as_float(e3.y);
        acc.x += v0.x * n0 + v1.x * n1 + v2.x * n2 + v3.x * n3;
        acc.y += v0.y * n0 + v1.y * n1 + v2.y * n2 + v3.y * n3;
        acc.z += v0.z * n0 + v1.z * n1 + v2.z * n2 + v3.z * n3;
        acc.w += v0.w * n0 + v1.w * n1 + v2.w * n2 + v3.w * n3;
    }
    for (; p < end; p++) {
        int2 e0 = g_edge[p];
        float4 v0 = *((const float4*)(srcb + (size_t)e0.x * (G4 * 4)) + j);
        float n0 = __int_as_float(e0.y);
        acc.x += v0.x * n0; acc.y += v0.y * n0;
        acc.z += v0.z * n0; acc.w += v0.w * n0;
    }

    float4* dp = (float4*)(dst + ((size_t)k * NN + n) * (G4 * 4)) + j;
    float4 cur = *dp;
    cur.x += acc.x; cur.y += acc.y; cur.z += acc.z; cur.w += acc.w;
    *dp = cur;
}

// ------- layer-1 epilogue: h = mean_k relu(bufC) (stride 64) -----------------
__global__ void combine_h_kernel() {
    int i = blockIdx.x * blockDim.x + threadIdx.x;
    if (i < NN * 64) {
        float a = g_bufC[i];
        float b = g_bufC[(size_t)NN * 64 + i];
        g_h[i] = 0.5f * (fmaxf(a, 0.f) + fmaxf(b, 0.f));
    }
}

// ---------------- final: mean_k relu + log_softmax (C=41, stride 48) ---------
__global__ void final_kernel(float* __restrict__ out) {
    const int warp = (int)((blockIdx.x * (size_t)blockDim.x + threadIdx.x) >> 5);
    const int lane = threadIdx.x & 31;
    if (warp >= NN) return;

    const size_t b0 = (size_t)warp * 48;
    const size_t b1 = ((size_t)NN + warp) * 48;

    float v1 = -1e30f, v2 = -1e30f;
    if (lane < 41)
        v1 = 0.5f * (fmaxf(g_bufC[b0 + lane], 0.f) + fmaxf(g_bufC[b1 + lane], 0.f));
    if (lane + 32 < 41)
        v2 = 0.5f * (fmaxf(g_bufC[b0 + lane + 32], 0.f) + fmaxf(g_bufC[b1 + lane + 32], 0.f));

    float m = fmaxf(v1, v2);
#pragma unroll
    for (int o = 16; o; o >>= 1) m = fmaxf(m, __shfl_xor_sync(0xFFFFFFFFu, m, o));

    float s = 0.f;
    if (lane < 41) s += expf(v1 - m);
    if (lane + 32 < 41) s += expf(v2 - m);
#pragma unroll
    for (int o = 16; o; o >>= 1) s += __shfl_xor_sync(0xFFFFFFFFu, s, o);

    const float l = m + logf(s);
    if (lane < 41) out[(size_t)warp * 41 + lane] = v1 - l;
    if (lane + 32 < 41) out[(size_t)warp * 41 + lane + 32] = v2 - l;
}

// ---------------- host driver: 3-stream overlapped schedule ------------------
extern "C" void kernel_launch(void* const* d_in, const int* in_sizes, int n_in,
                              void* d_out, int out_size) {
    const float* x       = (const float*)d_in[0];
    const int*   ei      = (const int*)d_in[1];   // int32 (JAX x64 disabled)
    const float* w1_init = (const float*)d_in[2];
    const float* w1_mid  = (const float*)d_in[3];  // [1,K,64,64]
    const float* w1_root = (const float*)d_in[4];  // [2,K,128,64]
    const float* b1      = (const float*)d_in[5];  // [2,K,1,64]
    const float* w2_init = (const float*)d_in[6];
    const float* w2_mid  = (const float*)d_in[7];  // [1,K,41,41]
    const float* w2_root = (const float*)d_in[8];  // [2,K,64,41]
    const float* b2      = (const float*)d_in[9];  // [2,K,1,41]
    float* out = (float*)d_out;
    const int E = in_sizes[1] / 2;

    // lazily-created side streams + events (host objects; graph replay uses
    // only the captured GPU nodes).  Non-blocking streams: cross-stream deps
    // are explicit events (required under graph capture).
    static bool inited = false;
    static cudaStream_t s1, s2;
    static cudaEvent_t evFork, evFill, evG2, evG4, evCH, evG6, evG8, evJ1;
    if (!inited) {
        cudaStreamCreateWithFlags(&s1, cudaStreamNonBlocking);
        cudaStreamCreateWithFlags(&s2, cudaStreamNonBlocking);
        cudaEventCreateWithFlags(&evFork, cudaEventDisableTiming);
        cudaEventCreateWithFlags(&evFill, cudaEventDisableTiming);
        cudaEventCreateWithFlags(&evG2,   cudaEventDisableTiming);
        cudaEventCreateWithFlags(&evG4,   cudaEventDisableTiming);
        cudaEventCreateWithFlags(&evCH,   cudaEventDisableTiming);
        cudaEventCreateWithFlags(&evG6,   cudaEventDisableTiming);
        cudaEventCreateWithFlags(&evG8,   cudaEventDisableTiming);
        cudaEventCreateWithFlags(&evJ1,   cudaEventDisableTiming);
        inited = true;
    }

    const int nb_n  = (NN + 255) / 256;
    const int nb_e  = (E + 255) / 256;
    const int nb_g1 = (int)(((long long)NN * 32 + 255) / 256);  // G4=16
    const int nb_g2 = (int)(((long long)NN * 24 + 255) / 256);  // G4=12

    const dim3 g_tc((NN + 255) / 256, KK);

    const int sm_128_64 = gemm_smem_bytes(128, 64);  // 69,888 > 48KB: opt-in
    const int sm_64_64  = gemm_smem_bytes(64, 64);
    const int sm_64_48  = gemm_smem_bytes(64, 48);
    const int sm_48_48  = gemm_smem_bytes(48, 48);

    cudaFuncSetAttribute(gemm_tc<128, 128, 64, false, false, false, -1, 0>,
                         cudaFuncAttributeMaxDynamicSharedMemorySize, sm_128_64);
    cudaFuncSetAttribute(gemm_tc<128, 128, 64, false, false, true, -1, 1>,
                         cudaFuncAttributeMaxDynamicSharedMemorySize, sm_128_64);
    cudaFuncSetAttribute(gemm_tc<128, 128, 64, false, false, true, -1, 3>,
                         cudaFuncAttributeMaxDynamicSharedMemorySize, sm_128_64);

    // ---- fork side streams from the (capturing) origin stream --------------
    cudaEventRecord(evFork, 0);
    cudaStreamWaitEvent(s1, evFork, 0);
    cudaStreamWaitEvent(s2, evFork, 0);

    // s2: CSR/prep chain (small grids; hides under the big GEMMs)
    zero_cnt_kernel<<<nb_n, 256, 0, s2>>>();
    count_kernel<<<nb_e, 256, 0, s2>>>(ei + E, E);
    dinv_kernel<<<nb_n, 256, 0, s2>>>();
    scanA_kernel<<<NB_SCAN, SCAN_CHUNK, 0, s2>>>();
    scanB_kernel<<<1, 256, 0, s2>>>();
    scanC_kernel<<<NB_SCAN, SCAN_CHUNK, 0, s2>>>();
    fill_kernel<<<nb_e, 256, 0, s2>>>(ei, E);
    cudaEventRecord(evFill, s2);

    // s1: root0 (x->bufA), then root1 (x->bufC) — both depend only on x
    gemm_tc<128, 128, 64, false, false, true, -1, 1>
        <<<g_tc, 256, sm_128_64, s1>>>(x, w1_root, 128, 64, b1, 64);
    cudaEventRecord(evG2, s1);
    gemm_tc<128, 128, 64, false, false, true, -1, 3>
        <<<g_tc, 256, sm_128_64, s1>>>(x, w1_root + (size_t)2 * 128 * 64,
                                       128, 64, b1 + 2 * 64, 64);
    cudaEventRecord(evG4, s1);

    // s0 (origin): init GEMM, then the dependent chain
    gemm_tc<128, 128, 64, false, false, false, -1, 0>
        <<<g_tc, 256, sm_128_64>>>(x, w1_init, 128, 64, nullptr, 0);
    cudaStreamWaitEvent(0, evG2, 0);
    cudaStreamWaitEvent(0, evFill, 0);
    gather_kernel<16, 0, 1><<<nb_g1, 256>>>();            // bufT -> bufA
    gemm_tc<64, 64, 64, true, true, false, 1, 0><<<g_tc, 256, sm_64_64>>>(
        nullptr, w1_mid, 64, 64, nullptr, 0);             // mid: bufA -> bufT
    cudaStreamWaitEvent(0, evG4, 0);
    gather_kernel<16, 0, 3><<<nb_g1, 256>>>();            // bufT -> bufC
    combine_h_kernel<<<(NN * 64 + 255) / 256, 256>>>();   // bufC -> h
    cudaEventRecord(evCH, 0);

    // s1: layer-2 root GEMMs (depend on h)
    cudaStreamWaitEvent(s1, evCH, 0);
    gemm_tc<64, 64, 48, false, false, true, 2, 1><<<g_tc, 256, sm_64_48, s1>>>(
        nullptr, w2_root, 64, 41, b2, 41);                // h -> bufA
    cudaEventRecord(evG6, s1);
    gemm_tc<64, 64, 48, false, false, true, 2, 3><<<g_tc, 256, sm_64_48, s1>>>(
        nullptr, w2_root + (size_t)2 * 64 * 41, 64, 41, b2 + 2 * 41, 41);
    cudaEventRecord(evG8, s1);                            // h -> bufC

    // s0: layer-2 chain
    gemm_tc<64, 64, 48, false, false, false, 2, 0><<<g_tc, 256, sm_64_48>>>(
        nullptr, w2_init, 64, 41, nullptr, 0);            // h -> bufT
    cudaStreamWaitEvent(0, evG6, 0);
    gather_kernel<12, 0, 1><<<nb_g2, 256>>>();            // bufT -> bufA
    gemm_tc<48, 48, 48, true, true, false, 1, 0><<<g_tc, 256, sm_48_48>>>(
        nullptr, w2_mid, 41, 41, nullptr, 0);             // mid2: bufA -> bufT
    cudaStreamWaitEvent(0, evG8, 0);
    gather_kernel<12, 0, 3><<<nb_g2, 256>>>();            // bufT -> bufC
    final_kernel<<<(NN * 32 + 255) / 256, 256>>>(out);    // bufC -> out

    // ---- join side streams back into the origin stream ---------------------
    cudaEventRecord(evJ1, s1);
    cudaStreamWaitEvent(0, evJ1, 0);
    // s2 was already joined via evFill, but re-join explicitly for safety
    cudaStreamWaitEvent(0, evFill, 0);
}

// round 13
// speedup vs baseline: 1.3136x; 1.0556x over previous
#include <cuda_runtime.h>
#include <cstdint>

#define NN 100000
#define KK 2
#define EMAX 1600000
#define SCAN_CHUNK 512
#define NB_SCAN ((NN + SCAN_CHUNK - 1) / SCAN_CHUNK)   // 196

// ---------------- scratch (static device globals; no allocation) -------------
__device__ float g_dinv[NN];
__device__ int   g_cnt[NN];
__device__ int   g_off[NN + 1];
__device__ int   g_cur[NN];
__device__ int   g_bsum[256];
__device__ int   g_boff[256];
__device__ int2  g_edge[EMAX];                       // (row, norm), CSR by col
__device__ float g_bufT[(size_t)KK * NN * 64 + 64];  // 51.2 MB
__device__ float g_bufA[(size_t)KK * NN * 64 + 64];  // 51.2 MB
__device__ float g_h[(size_t)NN * 64 + 64];          // 25.6 MB
__device__ float g_bufC[(size_t)KK * NN * 64 + 64];  // 51.2 MB (breaks WAR)

__device__ __forceinline__ float* sel_buf(int s) {
    return s == 0 ? g_bufT : (s == 1 ? g_bufA : (s == 2 ? g_h : g_bufC));
}

// ---------------- tf32 helpers -----------------------------------------------
__device__ __forceinline__ uint32_t f2tf(float f) {
    uint32_t r;
    asm("cvt.rna.tf32.f32 %0, %1;" : "=r"(r) : "f"(f));
    return r;
}

__device__ __forceinline__ void mma8(float* d, const uint32_t* a,
                                     uint32_t b0, uint32_t b1) {
    asm("mma.sync.aligned.m16n8k8.row.col.f32.tf32.tf32.f32 "
        "{%0,%1,%2,%3}, {%4,%5,%6,%7}, {%8,%9}, {%0,%1,%2,%3};"
        : "+f"(d[0]), "+f"(d[1]), "+f"(d[2]), "+f"(d[3])
        : "r"(a[0]), "r"(a[1]), "r"(a[2]), "r"(a[3]), "r"(b0), "r"(b1));
}

// ---------------- prep: degree, CSR build ------------------------------------
__global__ void zero_cnt_kernel() {
    int n = blockIdx.x * blockDim.x + threadIdx.x;
    if (n < NN) g_cnt[n] = 0;
}

__global__ void count_kernel(const int* __restrict__ col, int E) {
    int e = blockIdx.x * blockDim.x + threadIdx.x;
    if (e < E) atomicAdd(&g_cnt[col[e]], 1);
}

__global__ void dinv_kernel() {
    int n = blockIdx.x * blockDim.x + threadIdx.x;
    if (n < NN) {
        int c = g_cnt[n];
        g_dinv[n] = c > 0 ? rsqrtf((float)c) : 0.0f;
    }
}

__global__ void scanA_kernel() {
    __shared__ int s[SCAN_CHUNK];
    int t = threadIdx.x;
    int i = blockIdx.x * SCAN_CHUNK + t;
    s[t] = (i < NN) ? g_cnt[i] : 0;
    __syncthreads();
    for (int o = SCAN_CHUNK / 2; o > 0; o >>= 1) {
        if (t < o) s[t] += s[t + o];
        __syncthreads();
    }
    if (t == 0) g_bsum[blockIdx.x] = s[0];
}

__global__ void scanB_kernel() {
    __shared__ int s[256];
    int t = threadIdx.x;
    int val = (t < NB_SCAN) ? g_bsum[t] : 0;
    s[t] = val;
    __syncthreads();
    for (int o = 1; o < 256; o <<= 1) {
        int add = (t >= o) ? s[t - o] : 0;
        __syncthreads();
        s[t] += add;
        __syncthreads();
    }
    g_boff[t] = s[t] - val;
    if (t == NB_SCAN - 1) g_off[NN] = s[t];
}

__global__ void scanC_kernel() {
    __shared__ int s[SCAN_CHUNK];
    int t = threadIdx.x;
    int i = blockIdx.x * SCAN_CHUNK + t;
    int val = (i < NN) ? g_cnt[i] : 0;
    s[t] = val;
    __syncthreads();
    for (int o = 1; o < SCAN_CHUNK; o <<= 1) {
        int add = (t >= o) ? s[t - o] : 0;
        __syncthreads();
        s[t] += add;
        __syncthreads();
    }
    if (i < NN) {
        int excl = s[t] - val + g_boff[blockIdx.x];
        g_off[i] = excl;
        g_cur[i] = excl;
    }
}

__global__ void fill_kernel(const int* __restrict__ ei, int E) {
    int e = blockIdx.x * blockDim.x + threadIdx.x;
    if (e < E) {
        int r = ei[e];
        int c = ei[(size_t)E + e];
        float nrm = g_dinv[r] * g_dinv[c];
        int pos = atomicAdd(&g_cur[c], 1);
        g_edge[pos] = make_int2(r, __float_as_int(nrm));
    }
}

// ---------------- tensor-core GEMM (tf32 3-term, LDG.64 A, LDS.64 B) ---------
// k within each 8-step is PERMUTED: pair row (ks*4+c0) holds physical k
// {kb+2c0, kb+2c0+1} for both A and B sides (same product set -> identical
// math).  A: one float2 load per row per k-step (was 2 scalars).
template <int FP, int FS, int GP, bool PERK, bool RELUIN, bool HASB,
          int SRCSEL, int DSTSEL>
__global__ void gemm_tc(const float* __restrict__ Xext,
                        const float* __restrict__ W, int Fl, int Gl,
                        const float* __restrict__ Bias, int Bk) {
    constexpr int NCH = GP / 8;
    constexpr int KST = FP / 8;
    constexpr int BST = GP + 4;          // u64 row stride of pair arrays

    extern __shared__ unsigned char dsm_raw[];
    uint2* Wph = (uint2*)dsm_raw;                   // (FP/2)*BST u64 pairs
    uint2* Wpl = Wph + (FP / 2) * BST;
    float* Bsm = (float*)(Wpl + (FP / 2) * BST);

    const float* __restrict__ X = (SRCSEL < 0) ? Xext : sel_buf(SRCSEL);
    float* __restrict__ OUT = sel_buf(DSTSEL);

    const int kk = blockIdx.y;
    const int tid = threadIdx.x;
    const int wid = tid >> 5;
    const int lane = tid & 31;
    const int r0 = lane >> 2;    // 0..7
    const int c0 = lane & 3;     // 0..3

    // stage W as tf32 hi/lo pairs, k-permuted:
    // f -> pair row (f/8)*4 + ((f%8)>>1), slot j = (f%8)&1
    for (int i = tid; i < FP * GP; i += 256) {
        int f = i / GP, g = i % GP;
        float w = (f < Fl && g < Gl)
                      ? W[(size_t)kk * Fl * Gl + (size_t)f * Gl + g]
                      : 0.0f;
        uint32_t hi = f2tf(w);
        uint32_t lo = f2tf(w - __uint_as_float(hi));
        int kc = f & 7;
        int row = (f >> 3) * 4 + (kc >> 1);
        int j = kc & 1;
        ((uint32_t*)Wph)[(row * BST + g) * 2 + j] = hi;
        ((uint32_t*)Wpl)[(row * BST + g) * 2 + j] = lo;
    }
    if (tid < GP) Bsm[tid] = (HASB && tid < Gl) ? Bias[(size_t)kk * Bk + tid] : 0.0f;
    __syncthreads();

    const int mbase = blockIdx.x * 256 + wid * 32;

    const float* xp[4];
#pragma unroll
    for (int t = 0; t < 4; t++) {
        int n = mbase + t * 8 + r0;
        int nc = n < NN ? n : NN - 1;
        xp[t] = X + (PERK ? ((size_t)kk * NN + nc) * FS : (size_t)nc * FS);
    }

    float acc[2][NCH][4];
#pragma unroll
    for (int t = 0; t < 2; t++)
#pragma unroll
        for (int nc = 0; nc < NCH; nc++)
#pragma unroll
            for (int q = 0; q < 4; q++) acc[t][nc][q] = 0.0f;

#pragma unroll 2
    for (int ks = 0; ks < KST; ks++) {
        const int kb = ks * 8;
        uint32_t ahi[2][4], alo[2][4];
#pragma unroll
        for (int t = 0; t < 2; t++) {
            // float2 loads: cols {kb+2c0, kb+2c0+1} = logical {c0, c0+4}
            float2 p0 = *(const float2*)(xp[2 * t + 0] + kb + 2 * c0);
            float2 p1 = *(const float2*)(xp[2 * t + 1] + kb + 2 * c0);
            float v[4];
            v[0] = p0.x; v[1] = p1.x; v[2] = p0.y; v[3] = p1.y;
#pragma unroll
            for (int q = 0; q < 4; q++) {
                if (RELUIN) v[q] = fmaxf(v[q], 0.0f);
                uint32_t hi = f2tf(v[q]);
                ahi[t][q] = hi;
                alo[t][q] = f2tf(v[q] - __uint_as_float(hi));
            }
        }
#pragma unroll
        for (int nc = 0; nc < NCH; nc++) {
            const int bidx = (ks * 4 + c0) * BST + nc * 8 + r0;
            uint2 bh = Wph[bidx];
            uint2 bl = Wpl[bidx];
#pragma unroll
            for (int t = 0; t < 2; t++) {
                mma8(acc[t][nc], ahi[t], bh.x, bh.y);
                mma8(acc[t][nc], alo[t], bh.x, bh.y);
                mma8(acc[t][nc], ahi[t], bl.x, bl.y);
            }
        }
    }

#pragma unroll
    for (int t = 0; t < 2; t++) {
#pragma unroll
        for (int nc = 0; nc < NCH; nc++) {
            const int col = nc * 8 + 2 * c0;
            const float bx = Bsm[col], by = Bsm[col + 1];
            const int rowA = mbase + t * 16 + r0;
            const int rowB = rowA + 8;
            if (rowA < NN) {
                float2 v = make_float2(acc[t][nc][0] + bx, acc[t][nc][1] + by);
                *(float2*)(OUT + ((size_t)kk * NN + rowA) * GP + col) = v;
            }
            if (rowB < NN) {
                float2 v = make_float2(acc[t][nc][2] + bx, acc[t][nc][3] + by);
                *(float2*)(OUT + ((size_t)kk * NN + rowB) * GP + col) = v;
            }
        }
    }
}

static inline int gemm_smem_bytes(int FP, int GP) {
    return 2 * (FP / 2) * (GP + 4) * 8 + GP * 4;
}

// ---------------- CSR gather: dst[k,n] += sum_e norm_e * src[k,row_e] --------
// COMBINE: fuse h = mean_k relu(dst+acc) via shfl_xor(16); no dst writeback.
// (requires ITEMS == 32 so one warp == one node; only used for G4=16.)
template <int G4, int SRCSEL, int DSTSEL, bool COMBINE>
__global__ void gather_kernel() {
    const float* __restrict__ src = sel_buf(SRCSEL);
    float* __restrict__ dst = sel_buf(DSTSEL);

    constexpr int ITEMS = KK * G4;
    const long long t = blockIdx.x * (long long)blockDim.x + threadIdx.x;
    const int n = (int)(t / ITEMS);
    if (n >= NN) return;
    const int rem = (int)(t - (long long)n * ITEMS);
    const int k = rem / G4;
    const int j = rem - k * G4;

    int p = g_off[n];
    const int end = g_off[n + 1];

    const float* srcb = src + (size_t)k * NN * (G4 * 4);
    float4 acc = make_float4(0.f, 0.f, 0.f, 0.f);

    for (; p + 3 < end; p += 4) {
        int2 e0 = g_edge[p];
        int2 e1 = g_edge[p + 1];
        int2 e2 = g_edge[p + 2];
        int2 e3 = g_edge[p + 3];
        float4 v0 = *((const float4*)(srcb + (size_t)e0.x * (G4 * 4)) + j);
        float4 v1 = *((const float4*)(srcb + (size_t)e1.x * (G4 * 4)) + j);
        float4 v2 = *((const float4*)(srcb + (size_t)e2.x * (G4 * 4)) + j);
        float4 v3 = *((const float4*)(srcb + (size_t)e3.x * (G4 * 4)) + j);
        float n0 = __int_as_float(e0.y);
        float n1 = __int_as_float(e1.y);
        float n2 = __int_as_float(e2.y);
        float n3 = __int_as_float(e3.y);
        acc.x += v0.x * n0 + v1.x * n1 + v2.x * n2 + v3.x * n3;
        acc.y += v0.y * n0 + v1.y * n1 + v2.y * n2 + v3.y * n3;
        acc.z += v0.z * n0 + v1.z * n1 + v2.z * n2 + v3.z * n3;
        acc.w += v0.w * n0 + v1.w * n1 + v2.w * n2 + v3.w * n3;
    }
    for (; p < end; p++) {
        int2 e0 = g_edge[p];
        float4 v0 = *((const float4*)(srcb + (size_t)e0.x * (G4 * 4)) + j);
        float n0 = __int_as_float(e0.y);
        acc.x += v0.x * n0; acc.y += v0.y * n0;
        acc.z += v0.z * n0; acc.w += v0.w * n0;
    }

    float4* dp = (float4*)(dst + ((size_t)k * NN + n) * (G4 * 4)) + j;
    float4 cur = *dp;
    cur.x += acc.x; cur.y += acc.y; cur.z += acc.z; cur.w += acc.w;

    if (COMBINE) {
        // relu, swap k-halves (lane ^ 16), mean; lanes 0..15 write h[n].
        float4 r = make_float4(fmaxf(cur.x, 0.f), fmaxf(cur.y, 0.f),
                               fmaxf(cur.z, 0.f), fmaxf(cur.w, 0.f));
        float4 o;
        o.x = __shfl_xor_sync(0xFFFFFFFFu, r.x, 16);
        o.y = __shfl_xor_sync(0xFFFFFFFFu, r.y, 16);
        o.z = __shfl_xor_sync(0xFFFFFFFFu, r.z, 16);
        o.w = __shfl_xor_sync(0xFFFFFFFFu, r.w, 16);
        if (k == 0) {
            float4 hv = make_float4(0.5f * (r.x + o.x), 0.5f * (r.y + o.y),
                                    0.5f * (r.z + o.z), 0.5f * (r.w + o.w));
            *((float4*)(g_h + (size_t)n * 64) + j) = hv;
        }
    } else {
        *dp = cur;
    }
}

// ---------------- final: mean_k relu + log_softmax (C=41, stride 48) ---------
__global__ void final_kernel(float* __restrict__ out) {
    const int warp = (int)((blockIdx.x * (size_t)blockDim.x + threadIdx.x) >> 5);
    const int lane = threadIdx.x & 31;
    if (warp >= NN) return;

    const size_t b0 = (size_t)warp * 48;
    const size_t b1 = ((size_t)NN + warp) * 48;

    float v1 = -1e30f, v2 = -1e30f;
    if (lane < 41)
        v1 = 0.5f * (fmaxf(g_bufC[b0 + lane], 0.f) + fmaxf(g_bufC[b1 + lane], 0.f));
    if (lane + 32 < 41)
        v2 = 0.5f * (fmaxf(g_bufC[b0 + lane + 32], 0.f) + fmaxf(g_bufC[b1 + lane + 32], 0.f));

    float m = fmaxf(v1, v2);
#pragma unroll
    for (int o = 16; o; o >>= 1) m = fmaxf(m, __shfl_xor_sync(0xFFFFFFFFu, m, o));

    float s = 0.f;
    if (lane < 41) s += expf(v1 - m);
    if (lane + 32 < 41) s += expf(v2 - m);
#pragma unroll
    for (int o = 16; o; o >>= 1) s += __shfl_xor_sync(0xFFFFFFFFu, s, o);

    const float l = m + logf(s);
    if (lane < 41) out[(size_t)warp * 41 + lane] = v1 - l;
    if (lane + 32 < 41) out[(size_t)warp * 41 + lane + 32] = v2 - l;
}

// ---------------- host driver: 3-stream overlapped schedule ------------------
extern "C" void kernel_launch(void* const* d_in, const int* in_sizes, int n_in,
                              void* d_out, int out_size) {
    const float* x       = (const float*)d_in[0];
    const int*   ei      = (const int*)d_in[1];   // int32 (JAX x64 disabled)
    const float* w1_init = (const float*)d_in[2];
    const float* w1_mid  = (const float*)d_in[3];  // [1,K,64,64]
    const float* w1_root = (const float*)d_in[4];  // [2,K,128,64]
    const float* b1      = (const float*)d_in[5];  // [2,K,1,64]
    const float* w2_init = (const float*)d_in[6];
    const float* w2_mid  = (const float*)d_in[7];  // [1,K,41,41]
    const float* w2_root = (const float*)d_in[8];  // [2,K,64,41]
    const float* b2      = (const float*)d_in[9];  // [2,K,1,41]
    float* out = (float*)d_out;
    const int E = in_sizes[1] / 2;

    static bool inited = false;
    static cudaStream_t s1, s2;
    static cudaEvent_t evFork, evFill, evG2, evG4, evCH, evG6, evG8, evJ1;
    if (!inited) {
        cudaStreamCreateWithFlags(&s1, cudaStreamNonBlocking);
        cudaStreamCreateWithFlags(&s2, cudaStreamNonBlocking);
        cudaEventCreateWithFlags(&evFork, cudaEventDisableTiming);
        cudaEventCreateWithFlags(&evFill, cudaEventDisableTiming);
        cudaEventCreateWithFlags(&evG2,   cudaEventDisableTiming);
        cudaEventCreateWithFlags(&evG4,   cudaEventDisableTiming);
        cudaEventCreateWithFlags(&evCH,   cudaEventDisableTiming);
        cudaEventCreateWithFlags(&evG6,   cudaEventDisableTiming);
        cudaEventCreateWithFlags(&evG8,   cudaEventDisableTiming);
        cudaEventCreateWithFlags(&evJ1,   cudaEventDisableTiming);
        inited = true;
    }

    const int nb_n  = (NN + 255) / 256;
    const int nb_e  = (E + 255) / 256;
    const int nb_g1 = (int)(((long long)NN * 32 + 255) / 256);  // G4=16
    const int nb_g2 = (int)(((long long)NN * 24 + 255) / 256);  // G4=12

    const dim3 g_tc((NN + 255) / 256, KK);

    const int sm_128_64 = gemm_smem_bytes(128, 64);  // 69,888 > 48KB: opt-in
    const int sm_64_64  = gemm_smem_bytes(64, 64);
    const int sm_64_48  = gemm_smem_bytes(64, 48);
    const int sm_48_48  = gemm_smem_bytes(48, 48);

    cudaFuncSetAttribute(gemm_tc<128, 128, 64, false, false, false, -1, 0>,
                         cudaFuncAttributeMaxDynamicSharedMemorySize, sm_128_64);
    cudaFuncSetAttribute(gemm_tc<128, 128, 64, false, false, true, -1, 1>,
                         cudaFuncAttributeMaxDynamicSharedMemorySize, sm_128_64);
    cudaFuncSetAttribute(gemm_tc<128, 128, 64, false, false, true, -1, 3>,
                         cudaFuncAttributeMaxDynamicSharedMemorySize, sm_128_64);

    // ---- fork side streams from the (capturing) origin stream --------------
    cudaEventRecord(evFork, 0);
    cudaStreamWaitEvent(s1, evFork, 0);
    cudaStreamWaitEvent(s2, evFork, 0);

    // s2: CSR/prep chain (small grids; hides under the big GEMMs)
    zero_cnt_kernel<<<nb_n, 256, 0, s2>>>();
    count_kernel<<<nb_e, 256, 0, s2>>>(ei + E, E);
    dinv_kernel<<<nb_n, 256, 0, s2>>>();
    scanA_kernel<<<NB_SCAN, SCAN_CHUNK, 0, s2>>>();
    scanB_kernel<<<1, 256, 0, s2>>>();
    scanC_kernel<<<NB_SCAN, SCAN_CHUNK, 0, s2>>>();
    fill_kernel<<<nb_e, 256, 0, s2>>>(ei, E);
    cudaEventRecord(evFill, s2);

    // s1: root0 (x->bufA), then root1 (x->bufC) — both depend only on x
    gemm_tc<128, 128, 64, false, false, true, -1, 1>
        <<<g_tc, 256, sm_128_64, s1>>>(x, w1_root, 128, 64, b1, 64);
    cudaEventRecord(evG2, s1);
    gemm_tc<128, 128, 64, false, false, true, -1, 3>
        <<<g_tc, 256, sm_128_64, s1>>>(x, w1_root + (size_t)2 * 128 * 64,
                                       128, 64, b1 + 2 * 64, 64);
    cudaEventRecord(evG4, s1);

    // s0 (origin): init GEMM, then the dependent chain
    gemm_tc<128, 128, 64, false, false, false, -1, 0>
        <<<g_tc, 256, sm_128_64>>>(x, w1_init, 128, 64, nullptr, 0);
    cudaStreamWaitEvent(0, evG2, 0);
    cudaStreamWaitEvent(0, evFill, 0);
    gather_kernel<16, 0, 1, false><<<nb_g1, 256>>>();     // bufT -> bufA
    gemm_tc<64, 64, 64, true, true, false, 1, 0><<<g_tc, 256, sm_64_64>>>(
        nullptr, w1_mid, 64, 64, nullptr, 0);             // mid: bufA -> bufT
    cudaStreamWaitEvent(0, evG4, 0);
    gather_kernel<16, 0, 3, true><<<nb_g1, 256>>>();      // bufT+bufC -> h (fused)
    cudaEventRecord(evCH, 0);

    // s1: layer-2 root GEMMs (depend on h)
    cudaStreamWaitEvent(s1, evCH, 0);
    gemm_tc<64, 64, 48, false, false, true, 2, 1><<<g_tc, 256, sm_64_48, s1>>>(
        nullptr, w2_root, 64, 41, b2, 41);                // h -> bufA
    cudaEventRecord(evG6, s1);
    gemm_tc<64, 64, 48, false, false, true, 2, 3><<<g_tc, 256, sm_64_48, s1>>>(
        nullptr, w2_root + (size_t)2 * 64 * 41, 64, 41, b2 + 2 * 41, 41);
    cudaEventRecord(evG8, s1);                            // h -> bufC

    // s0: layer-2 chain
    gemm_tc<64, 64, 48, false, false, false, 2, 0><<<g_tc, 256, sm_64_48>>>(
        nullptr, w2_init, 64, 41, nullptr, 0);            // h -> bufT
    cudaStreamWaitEvent(0, evG6, 0);
    gather_kernel<12, 0, 1, false><<<nb_g2, 256>>>();     // bufT -> bufA
    gemm_tc<48, 48, 48, true, true, false, 1, 0><<<g_tc, 256, sm_48_48>>>(
        nullptr, w2_mid, 41, 41, nullptr, 0);             // mid2: bufA -> bufT
    cudaStreamWaitEvent(0, evG8, 0);
    gather_kernel<12, 0, 3, false><<<nb_g2, 256>>>();     // bufT -> bufC
    final_kernel<<<(NN * 32 + 255) / 256, 256>>>(out);    // bufC -> out

    // ---- join side streams back into the origin stream ---------------------
    cudaEventRecord(evJ1, s1);
    cudaStreamWaitEvent(0, evJ1, 0);
    cudaStreamWaitEvent(0, evFill, 0);
}

// round 14
// speedup vs baseline: 1.4986x; 1.1408x over previous
#include <cuda_runtime.h>
#include <cuda_fp16.h>
#include <cstdint>

#define NN 100000
#define KK 2
#define EMAX 1600000
#define SCAN_CHUNK 512
#define NB_SCAN ((NN + SCAN_CHUNK - 1) / SCAN_CHUNK)   // 196

// ---------------- scratch (static device globals; no allocation) -------------
__device__ float g_dinv[NN];
__device__ int   g_cnt[NN];
__device__ int   g_off[NN + 1];
__device__ int   g_cur[NN];
__device__ int   g_bsum[256];
__device__ int   g_boff[256];
__device__ int2  g_edge[EMAX];                       // (row, norm), CSR by col
__device__ float g_bufT[(size_t)KK * NN * 64 + 64];  // fp16-packed gather src
__device__ float g_bufA[(size_t)KK * NN * 64 + 64];  // 51.2 MB fp32
__device__ float g_h[(size_t)NN * 64 + 64];          // 25.6 MB fp32
__device__ float g_bufC[(size_t)KK * NN * 64 + 64];  // 51.2 MB fp32

__device__ __forceinline__ float* sel_buf(int s) {
    return s == 0 ? g_bufT : (s == 1 ? g_bufA : (s == 2 ? g_h : g_bufC));
}

// ---------------- tf32 helpers -----------------------------------------------
__device__ __forceinline__ uint32_t f2tf(float f) {
    uint32_t r;
    asm("cvt.rna.tf32.f32 %0, %1;" : "=r"(r) : "f"(f));
    return r;
}

__device__ __forceinline__ void mma8(float* d, const uint32_t* a,
                                     uint32_t b0, uint32_t b1) {
    asm("mma.sync.aligned.m16n8k8.row.col.f32.tf32.tf32.f32 "
        "{%0,%1,%2,%3}, {%4,%5,%6,%7}, {%8,%9}, {%0,%1,%2,%3};"
        : "+f"(d[0]), "+f"(d[1]), "+f"(d[2]), "+f"(d[3])
        : "r"(a[0]), "r"(a[1]), "r"(a[2]), "r"(a[3]), "r"(b0), "r"(b1));
}

// ---------------- prep: degree, CSR build ------------------------------------
__global__ void zero_cnt_kernel() {
    int n = blockIdx.x * blockDim.x + threadIdx.x;
    if (n < NN) g_cnt[n] = 0;
}

__global__ void count_kernel(const int* __restrict__ col, int E) {
    int e = blockIdx.x * blockDim.x + threadIdx.x;
    if (e < E) atomicAdd(&g_cnt[col[e]], 1);
}

__global__ void dinv_kernel() {
    int n = blockIdx.x * blockDim.x + threadIdx.x;
    if (n < NN) {
        int c = g_cnt[n];
        g_dinv[n] = c > 0 ? rsqrtf((float)c) : 0.0f;
    }
}

__global__ void scanA_kernel() {
    __shared__ int s[SCAN_CHUNK];
    int t = threadIdx.x;
    int i = blockIdx.x * SCAN_CHUNK + t;
    s[t] = (i < NN) ? g_cnt[i] : 0;
    __syncthreads();
    for (int o = SCAN_CHUNK / 2; o > 0; o >>= 1) {
        if (t < o) s[t] += s[t + o];
        __syncthreads();
    }
    if (t == 0) g_bsum[blockIdx.x] = s[0];
}

__global__ void scanB_kernel() {
    __shared__ int s[256];
    int t = threadIdx.x;
    int val = (t < NB_SCAN) ? g_bsum[t] : 0;
    s[t] = val;
    __syncthreads();
    for (int o = 1; o < 256; o <<= 1) {
        int add = (t >= o) ? s[t - o] : 0;
        __syncthreads();
        s[t] += add;
        __syncthreads();
    }
    g_boff[t] = s[t] - val;
    if (t == NB_SCAN - 1) g_off[NN] = s[t];
}

__global__ void scanC_kernel() {
    __shared__ int s[SCAN_CHUNK];
    int t = threadIdx.x;
    int i = blockIdx.x * SCAN_CHUNK + t;
    int val = (i < NN) ? g_cnt[i] : 0;
    s[t] = val;
    __syncthreads();
    for (int o = 1; o < SCAN_CHUNK; o <<= 1) {
        int add = (t >= o) ? s[t - o] : 0;
        __syncthreads();
        s[t] += add;
        __syncthreads();
    }
    if (i < NN) {
        int excl = s[t] - val + g_boff[blockIdx.x];
        g_off[i] = excl;
        g_cur[i] = excl;
    }
}

__global__ void fill_kernel(const int* __restrict__ ei, int E) {
    int e = blockIdx.x * blockDim.x + threadIdx.x;
    if (e < E) {
        int r = ei[e];
        int c = ei[(size_t)E + e];
        float nrm = g_dinv[r] * g_dinv[c];
        int pos = atomicAdd(&g_cur[c], 1);
        g_edge[pos] = make_int2(r, __float_as_int(nrm));
    }
}

// ---------------- tensor-core GEMM (tf32 3-term, LDG.64 A, LDS.64 B) ---------
// k within each 8-step is PERMUTED: pair row (ks*4+c0) holds physical k
// {kb+2c0, kb+2c0+1} (same product set -> identical math).
// OUTH: store output as fp16 (__half2 per float2 pair) — gather-source path.
template <int FP, int FS, int GP, bool PERK, bool RELUIN, bool HASB, bool OUTH,
          int SRCSEL, int DSTSEL>
__global__ void gemm_tc(const float* __restrict__ Xext,
                        const float* __restrict__ W, int Fl, int Gl,
                        const float* __restrict__ Bias, int Bk) {
    constexpr int NCH = GP / 8;
    constexpr int KST = FP / 8;
    constexpr int BST = GP + 4;          // u64 row stride of pair arrays

    extern __shared__ unsigned char dsm_raw[];
    uint2* Wph = (uint2*)dsm_raw;                   // (FP/2)*BST u64 pairs
    uint2* Wpl = Wph + (FP / 2) * BST;
    float* Bsm = (float*)(Wpl + (FP / 2) * BST);

    const float* __restrict__ X = (SRCSEL < 0) ? Xext : sel_buf(SRCSEL);
    float* __restrict__ OUT = sel_buf(DSTSEL);

    const int kk = blockIdx.y;
    const int tid = threadIdx.x;
    const int wid = tid >> 5;
    const int lane = tid & 31;
    const int r0 = lane >> 2;    // 0..7
    const int c0 = lane & 3;     // 0..3

    // stage W as tf32 hi/lo pairs, k-permuted:
    // f -> pair row (f/8)*4 + ((f%8)>>1), slot j = (f%8)&1
    for (int i = tid; i < FP * GP; i += 256) {
        int f = i / GP, g = i % GP;
        float w = (f < Fl && g < Gl)
                      ? W[(size_t)kk * Fl * Gl + (size_t)f * Gl + g]
                      : 0.0f;
        uint32_t hi = f2tf(w);
        uint32_t lo = f2tf(w - __uint_as_float(hi));
        int kc = f & 7;
        int row = (f >> 3) * 4 + (kc >> 1);
        int j = kc & 1;
        ((uint32_t*)Wph)[(row * BST + g) * 2 + j] = hi;
        ((uint32_t*)Wpl)[(row * BST + g) * 2 + j] = lo;
    }
    if (tid < GP) Bsm[tid] = (HASB && tid < Gl) ? Bias[(size_t)kk * Bk + tid] : 0.0f;
    __syncthreads();

    const int mbase = blockIdx.x * 256 + wid * 32;

    const float* xp[4];
#pragma unroll
    for (int t = 0; t < 4; t++) {
        int n = mbase + t * 8 + r0;
        int nc = n < NN ? n : NN - 1;
        xp[t] = X + (PERK ? ((size_t)kk * NN + nc) * FS : (size_t)nc * FS);
    }

    float acc[2][NCH][4];
#pragma unroll
    for (int t = 0; t < 2; t++)
#pragma unroll
        for (int nc = 0; nc < NCH; nc++)
#pragma unroll
            for (int q = 0; q < 4; q++) acc[t][nc][q] = 0.0f;

#pragma unroll 2
    for (int ks = 0; ks < KST; ks++) {
        const int kb = ks * 8;
        uint32_t ahi[2][4], alo[2][4];
#pragma unroll
        for (int t = 0; t < 2; t++) {
            float2 p0 = *(const float2*)(xp[2 * t + 0] + kb + 2 * c0);
            float2 p1 = *(const float2*)(xp[2 * t + 1] + kb + 2 * c0);
            float v[4];
            v[0] = p0.x; v[1] = p1.x; v[2] = p0.y; v[3] = p1.y;
#pragma unroll
            for (int q = 0; q < 4; q++) {
                if (RELUIN) v[q] = fmaxf(v[q], 0.0f);
                uint32_t hi = f2tf(v[q]);
                ahi[t][q] = hi;
                alo[t][q] = f2tf(v[q] - __uint_as_float(hi));
            }
        }
#pragma unroll
        for (int nc = 0; nc < NCH; nc++) {
            const int bidx = (ks * 4 + c0) * BST + nc * 8 + r0;
            uint2 bh = Wph[bidx];
            uint2 bl = Wpl[bidx];
#pragma unroll
            for (int t = 0; t < 2; t++) {
                mma8(acc[t][nc], ahi[t], bh.x, bh.y);
                mma8(acc[t][nc], alo[t], bh.x, bh.y);
                mma8(acc[t][nc], ahi[t], bl.x, bl.y);
            }
        }
    }

#pragma unroll
    for (int t = 0; t < 2; t++) {
#pragma unroll
        for (int nc = 0; nc < NCH; nc++) {
            const int col = nc * 8 + 2 * c0;
            const float bx = Bsm[col], by = Bsm[col + 1];
            const int rowA = mbase + t * 16 + r0;
            const int rowB = rowA + 8;
            if (rowA < NN) {
                float vx = acc[t][nc][0] + bx, vy = acc[t][nc][1] + by;
                if (OUTH) {
                    __half2* o = (__half2*)((__half*)OUT +
                        ((size_t)kk * NN + rowA) * GP + col);
                    *o = __floats2half2_rn(vx, vy);
                } else {
                    *(float2*)(OUT + ((size_t)kk * NN + rowA) * GP + col) =
                        make_float2(vx, vy);
                }
            }
            if (rowB < NN) {
                float vx = acc[t][nc][2] + bx, vy = acc[t][nc][3] + by;
                if (OUTH) {
                    __half2* o = (__half2*)((__half*)OUT +
                        ((size_t)kk * NN + rowB) * GP + col);
                    *o = __floats2half2_rn(vx, vy);
                } else {
                    *(float2*)(OUT + ((size_t)kk * NN + rowB) * GP + col) =
                        make_float2(vx, vy);
                }
            }
        }
    }
}

static inline int gemm_smem_bytes(int FP, int GP) {
    return 2 * (FP / 2) * (GP + 4) * 8 + GP * 4;
}

// ---------------- CSR gather (fp16 src): dst[k,n] += sum norm*src[k,row] -----
// src rows are fp16 (written by OUTH GEMMs).  Lane chunk = 4 halfs (8B LDG).
// COMBINE: fuse h = mean_k relu(dst+acc) via shfl_xor(16) (ITEMS==32 only).
template <int G4, int SRCSEL, int DSTSEL, bool COMBINE>
__global__ void gather_kernel() {
    const __half* __restrict__ src = (const __half*)sel_buf(SRCSEL);
    float* __restrict__ dst = sel_buf(DSTSEL);

    constexpr int ITEMS = KK * G4;
    const long long t = blockIdx.x * (long long)blockDim.x + threadIdx.x;
    const int n = (int)(t / ITEMS);
    if (n >= NN) return;
    const int rem = (int)(t - (long long)n * ITEMS);
    const int k = rem / G4;
    const int j = rem - k * G4;

    int p = g_off[n];
    const int end = g_off[n + 1];

    const __half* srcb = src + (size_t)k * NN * (G4 * 4);
    float4 acc = make_float4(0.f, 0.f, 0.f, 0.f);

#define GATH_LOAD(vv, ee)                                                     \
    {                                                                         \
        const __half2* hp = (const __half2*)(srcb +                           \
            (size_t)(ee).x * (G4 * 4) + j * 4);                               \
        float2 a = __half22float2(hp[0]);                                     \
        float2 b = __half22float2(hp[1]);                                     \
        vv = make_float4(a.x, a.y, b.x, b.y);                                 \
    }

    for (; p + 3 < end; p += 4) {
        int2 e0 = g_edge[p];
        int2 e1 = g_edge[p + 1];
        int2 e2 = g_edge[p + 2];
        int2 e3 = g_edge[p + 3];
        float4 v0, v1, v2, v3;
        GATH_LOAD(v0, e0) GATH_LOAD(v1, e1) GATH_LOAD(v2, e2) GATH_LOAD(v3, e3)
        float n0 = __int_as_float(e0.y);
        float n1 = __int_as_float(e1.y);
        float n2 = __int_as_float(e2.y);
        float n3 = __int_as_float(e3.y);
        acc.x += v0.x * n0 + v1.x * n1 + v2.x * n2 + v3.x * n3;
        acc.y += v0.y * n0 + v1.y * n1 + v2.y * n2 + v3.y * n3;
        acc.z += v0.z * n0 + v1.z * n1 + v2.z * n2 + v3.z * n3;
        acc.w += v0.w * n0 + v1.w * n1 + v2.w * n2 + v3.w * n3;
    }
    for (; p < end; p++) {
        int2 e0 = g_edge[p];
        float4 v0;
        GATH_LOAD(v0, e0)
        float n0 = __int_as_float(e0.y);
        acc.x += v0.x * n0; acc.y += v0.y * n0;
        acc.z += v0.z * n0; acc.w += v0.w * n0;
    }
#undef GATH_LOAD

    float4* dp = (float4*)(dst + ((size_t)k * NN + n) * (G4 * 4)) + j;
    float4 cur = *dp;
    cur.x += acc.x; cur.y += acc.y; cur.z += acc.z; cur.w += acc.w;

    if (COMBINE) {
        float4 r = make_float4(fmaxf(cur.x, 0.f), fmaxf(cur.y, 0.f),
                               fmaxf(cur.z, 0.f), fmaxf(cur.w, 0.f));
        float4 o;
        o.x = __shfl_xor_sync(0xFFFFFFFFu, r.x, 16);
        o.y = __shfl_xor_sync(0xFFFFFFFFu, r.y, 16);
        o.z = __shfl_xor_sync(0xFFFFFFFFu, r.z, 16);
        o.w = __shfl_xor_sync(0xFFFFFFFFu, r.w, 16);
        if (k == 0) {
            float4 hv = make_float4(0.5f * (r.x + o.x), 0.5f * (r.y + o.y),
                                    0.5f * (r.z + o.z), 0.5f * (r.w + o.w));
            *((float4*)(g_h + (size_t)n * 64) + j) = hv;
        }
    } else {
        *dp = cur;
    }
}

// ---------------- final: mean_k relu + log_softmax (C=41, stride 48) ---------
__global__ void final_kernel(float* __restrict__ out) {
    const int warp = (int)((blockIdx.x * (size_t)blockDim.x + threadIdx.x) >> 5);
    const int lane = threadIdx.x & 31;
    if (warp >= NN) return;

    const size_t b0 = (size_t)warp * 48;
    const size_t b1 = ((size_t)NN + warp) * 48;

    float v1 = -1e30f, v2 = -1e30f;
    if (lane < 41)
        v1 = 0.5f * (fmaxf(g_bufC[b0 + lane], 0.f) + fmaxf(g_bufC[b1 + lane], 0.f));
    if (lane + 32 < 41)
        v2 = 0.5f * (fmaxf(g_bufC[b0 + lane + 32], 0.f) + fmaxf(g_bufC[b1 + lane + 32], 0.f));

    float m = fmaxf(v1, v2);
#pragma unroll
    for (int o = 16; o; o >>= 1) m = fmaxf(m, __shfl_xor_sync(0xFFFFFFFFu, m, o));

    float s = 0.f;
    if (lane < 41) s += expf(v1 - m);
    if (lane + 32 < 41) s += expf(v2 - m);
#pragma unroll
    for (int o = 16; o; o >>= 1) s += __shfl_xor_sync(0xFFFFFFFFu, s, o);

    const float l = m + logf(s);
    if (lane < 41) out[(size_t)warp * 41 + lane] = v1 - l;
    if (lane + 32 < 41) out[(size_t)warp * 41 + lane + 32] = v2 - l;
}

// ---------------- host driver: 3-stream overlapped schedule ------------------
extern "C" void kernel_launch(void* const* d_in, const int* in_sizes, int n_in,
                              void* d_out, int out_size) {
    const float* x       = (const float*)d_in[0];
    const int*   ei      = (const int*)d_in[1];   // int32 (JAX x64 disabled)
    const float* w1_init = (const float*)d_in[2];
    const float* w1_mid  = (const float*)d_in[3];  // [1,K,64,64]
    const float* w1_root = (const float*)d_in[4];  // [2,K,128,64]
    const float* b1      = (const float*)d_in[5];  // [2,K,1,64]
    const float* w2_init = (const float*)d_in[6];
    const float* w2_mid  = (const float*)d_in[7];  // [1,K,41,41]
    const float* w2_root = (const float*)d_in[8];  // [2,K,64,41]
    const float* b2      = (const float*)d_in[9];  // [2,K,1,41]
    float* out = (float*)d_out;
    const int E = in_sizes[1] / 2;

    static bool inited = false;
    static cudaStream_t s1, s2;
    static cudaEvent_t evFork, evFill, evG2, evG4, evCH, evG6, evG8, evJ1;
    if (!inited) {
        cudaStreamCreateWithFlags(&s1, cudaStreamNonBlocking);
        cudaStreamCreateWithFlags(&s2, cudaStreamNonBlocking);
        cudaEventCreateWithFlags(&evFork, cudaEventDisableTiming);
        cudaEventCreateWithFlags(&evFill, cudaEventDisableTiming);
        cudaEventCreateWithFlags(&evG2,   cudaEventDisableTiming);
        cudaEventCreateWithFlags(&evG4,   cudaEventDisableTiming);
        cudaEventCreateWithFlags(&evCH,   cudaEventDisableTiming);
        cudaEventCreateWithFlags(&evG6,   cudaEventDisableTiming);
        cudaEventCreateWithFlags(&evG8,   cudaEventDisableTiming);
        cudaEventCreateWithFlags(&evJ1,   cudaEventDisableTiming);
        inited = true;
    }

    const int nb_n  = (NN + 255) / 256;
    const int nb_e  = (E + 255) / 256;
    const int nb_g1 = (int)(((long long)NN * 32 + 255) / 256);  // G4=16
    const int nb_g2 = (int)(((long long)NN * 24 + 255) / 256);  // G4=12

    const dim3 g_tc((NN + 255) / 256, KK);

    const int sm_128_64 = gemm_smem_bytes(128, 64);  // 69,888 > 48KB: opt-in
    const int sm_64_64  = gemm_smem_bytes(64, 64);
    const int sm_64_48  = gemm_smem_bytes(64, 48);
    const int sm_48_48  = gemm_smem_bytes(48, 48);

    cudaFuncSetAttribute(gemm_tc<128, 128, 64, false, false, false, true, -1, 0>,
                         cudaFuncAttributeMaxDynamicSharedMemorySize, sm_128_64);
    cudaFuncSetAttribute(gemm_tc<128, 128, 64, false, false, true, false, -1, 1>,
                         cudaFuncAttributeMaxDynamicSharedMemorySize, sm_128_64);
    cudaFuncSetAttribute(gemm_tc<128, 128, 64, false, false, true, false, -1, 3>,
                         cudaFuncAttributeMaxDynamicSharedMemorySize, sm_128_64);

    // ---- fork side streams from the (capturing) origin stream --------------
    cudaEventRecord(evFork, 0);
    cudaStreamWaitEvent(s1, evFork, 0);
    cudaStreamWaitEvent(s2, evFork, 0);

    // s2: CSR/prep chain (small grids; hides under the big GEMMs)
    zero_cnt_kernel<<<nb_n, 256, 0, s2>>>();
    count_kernel<<<nb_e, 256, 0, s2>>>(ei + E, E);
    dinv_kernel<<<nb_n, 256, 0, s2>>>();
    scanA_kernel<<<NB_SCAN, SCAN_CHUNK, 0, s2>>>();
    scanB_kernel<<<1, 256, 0, s2>>>();
    scanC_kernel<<<NB_SCAN, SCAN_CHUNK, 0, s2>>>();
    fill_kernel<<<nb_e, 256, 0, s2>>>(ei, E);
    cudaEventRecord(evFill, s2);

    // s1: root0 (x->bufA fp32), root1 (x->bufC fp32)
    gemm_tc<128, 128, 64, false, false, true, false, -1, 1>
        <<<g_tc, 256, sm_128_64, s1>>>(x, w1_root, 128, 64, b1, 64);
    cudaEventRecord(evG2, s1);
    gemm_tc<128, 128, 64, false, false, true, false, -1, 3>
        <<<g_tc, 256, sm_128_64, s1>>>(x, w1_root + (size_t)2 * 128 * 64,
                                       128, 64, b1 + 2 * 64, 64);
    cudaEventRecord(evG4, s1);

    // s0 (origin): init GEMM (x->bufT fp16), then the dependent chain
    gemm_tc<128, 128, 64, false, false, false, true, -1, 0>
        <<<g_tc, 256, sm_128_64>>>(x, w1_init, 128, 64, nullptr, 0);
    cudaStreamWaitEvent(0, evG2, 0);
    cudaStreamWaitEvent(0, evFill, 0);
    gather_kernel<16, 0, 1, false><<<nb_g1, 256>>>();     // bufT(h16) -> bufA
    gemm_tc<64, 64, 64, true, true, false, true, 1, 0><<<g_tc, 256, sm_64_64>>>(
        nullptr, w1_mid, 64, 64, nullptr, 0);             // mid: bufA -> bufT h16
    cudaStreamWaitEvent(0, evG4, 0);
    gather_kernel<16, 0, 3, true><<<nb_g1, 256>>>();      // bufT+bufC -> h (fused)
    cudaEventRecord(evCH, 0);

    // s1: layer-2 root GEMMs (depend on h)
    cudaStreamWaitEvent(s1, evCH, 0);
    gemm_tc<64, 64, 48, false, false, true, false, 2, 1>
        <<<g_tc, 256, sm_64_48, s1>>>(nullptr, w2_root, 64, 41, b2, 41);
    cudaEventRecord(evG6, s1);
    gemm_tc<64, 64, 48, false, false, true, false, 2, 3>
        <<<g_tc, 256, sm_64_48, s1>>>(nullptr, w2_root + (size_t)2 * 64 * 41,
                                      64, 41, b2 + 2 * 41, 41);
    cudaEventRecord(evG8, s1);                            // h -> bufC

    // s0: layer-2 chain
    gemm_tc<64, 64, 48, false, false, false, true, 2, 0><<<g_tc, 256, sm_64_48>>>(
        nullptr, w2_init, 64, 41, nullptr, 0);            // h -> bufT h16
    cudaStreamWaitEvent(0, evG6, 0);
    gather_kernel<12, 0, 1, false><<<nb_g2, 256>>>();     // bufT(h16) -> bufA
    gemm_tc<48, 48, 48, true, true, false, true, 1, 0><<<g_tc, 256, sm_48_48>>>(
        nullptr, w2_mid, 41, 41, nullptr, 0);             // mid2: bufA -> bufT h16
    cudaStreamWaitEvent(0, evG8, 0);
    gather_kernel<12, 0, 3, false><<<nb_g2, 256>>>();     // bufT(h16) -> bufC
    final_kernel<<<(NN * 32 + 255) / 256, 256>>>(out);    // bufC -> out

    // ---- join side streams back into the origin stream ---------------------
    cudaEventRecord(evJ1, s1);
    cudaStreamWaitEvent(0, evJ1, 0);
    cudaStreamWaitEvent(0, evFill, 0);
}

// round 15
// speedup vs baseline: 1.5375x; 1.0260x over previous
#include <cuda_runtime.h>
#include <cuda_fp16.h>
#include <cstdint>
#include <cstring>

#define NN 100000
#define KK 2
#define EMAX 1600000
#define SCAN_CHUNK 512
#define NB_SCAN ((NN + SCAN_CHUNK - 1) / SCAN_CHUNK)   // 196

// ---------------- scratch (static device globals; no allocation) -------------
__device__ float g_dinv[NN];
__device__ int   g_cnt[NN];
__device__ int   g_off[NN + 1];
__device__ int   g_cur[NN];
__device__ int   g_bsum[256];
__device__ int   g_boff[256];
__device__ int2  g_edge[EMAX];                       // (row, norm), CSR by col
__device__ float g_bufT[(size_t)KK * NN * 64 + 64];  // fp16-packed gather src
__device__ float g_bufA[(size_t)KK * NN * 64 + 64];  // 51.2 MB fp32
__device__ float g_h[(size_t)NN * 64 + 64];          // 25.6 MB fp32
__device__ float g_bufC[(size_t)KK * NN * 64 + 64];  // 51.2 MB fp32

__device__ __forceinline__ float* sel_buf(int s) {
    return s == 0 ? g_bufT : (s == 1 ? g_bufA : (s == 2 ? g_h : g_bufC));
}

// ---------------- fp16 helpers -----------------------------------------------
__device__ __forceinline__ uint32_t h2u(__half2 h) {
    uint32_t u;
    memcpy(&u, &h, 4);
    return u;
}

// m16n8k16 f16 MMA, f32 accumulate
__device__ __forceinline__ void mma16(float* d, const uint32_t* a,
                                      uint32_t b0, uint32_t b1) {
    asm("mma.sync.aligned.m16n8k16.row.col.f32.f16.f16.f32 "
        "{%0,%1,%2,%3}, {%4,%5,%6,%7}, {%8,%9}, {%0,%1,%2,%3};"
        : "+f"(d[0]), "+f"(d[1]), "+f"(d[2]), "+f"(d[3])
        : "r"(a[0]), "r"(a[1]), "r"(a[2]), "r"(a[3]), "r"(b0), "r"(b1));
}

// ---------------- prep: degree, CSR build ------------------------------------
__global__ void zero_cnt_kernel() {
    int n = blockIdx.x * blockDim.x + threadIdx.x;
    if (n < NN) g_cnt[n] = 0;
}

__global__ void count_kernel(const int* __restrict__ col, int E) {
    int e = blockIdx.x * blockDim.x + threadIdx.x;
    if (e < E) atomicAdd(&g_cnt[col[e]], 1);
}

__global__ void dinv_kernel() {
    int n = blockIdx.x * blockDim.x + threadIdx.x;
    if (n < NN) {
        int c = g_cnt[n];
        g_dinv[n] = c > 0 ? rsqrtf((float)c) : 0.0f;
    }
}

__global__ void scanA_kernel() {
    __shared__ int s[SCAN_CHUNK];
    int t = threadIdx.x;
    int i = blockIdx.x * SCAN_CHUNK + t;
    s[t] = (i < NN) ? g_cnt[i] : 0;
    __syncthreads();
    for (int o = SCAN_CHUNK / 2; o > 0; o >>= 1) {
        if (t < o) s[t] += s[t + o];
        __syncthreads();
    }
    if (t == 0) g_bsum[blockIdx.x] = s[0];
}

__global__ void scanB_kernel() {
    __shared__ int s[256];
    int t = threadIdx.x;
    int val = (t < NB_SCAN) ? g_bsum[t] : 0;
    s[t] = val;
    __syncthreads();
    for (int o = 1; o < 256; o <<= 1) {
        int add = (t >= o) ? s[t - o] : 0;
        __syncthreads();
        s[t] += add;
        __syncthreads();
    }
    g_boff[t] = s[t] - val;
    if (t == NB_SCAN - 1) g_off[NN] = s[t];
}

__global__ void scanC_kernel() {
    __shared__ int s[SCAN_CHUNK];
    int t = threadIdx.x;
    int i = blockIdx.x * SCAN_CHUNK + t;
    int val = (i < NN) ? g_cnt[i] : 0;
    s[t] = val;
    __syncthreads();
    for (int o = 1; o < SCAN_CHUNK; o <<= 1) {
        int add = (t >= o) ? s[t - o] : 0;
        __syncthreads();
        s[t] += add;
        __syncthreads();
    }
    if (i < NN) {
        int excl = s[t] - val + g_boff[blockIdx.x];
        g_off[i] = excl;
        g_cur[i] = excl;
    }
}

__global__ void fill_kernel(const int* __restrict__ ei, int E) {
    int e = blockIdx.x * blockDim.x + threadIdx.x;
    if (e < E) {
        int r = ei[e];
        int c = ei[(size_t)E + e];
        float nrm = g_dinv[r] * g_dinv[c];
        int pos = atomicAdd(&g_cur[c], 1);
        g_edge[pos] = make_int2(r, __float_as_int(nrm));
    }
}

// ---------------- tensor-core GEMM (fp16 3-term split, m16n8k16) -------------
// Identical math precision to tf32 3-term (u = 2^-11 both; dropped alo*blo
// term ~ u^2 = 2.4e-7) but half the MMA instructions (k16) and half W smem.
// W staged as fp16 hi/lo uint2 pair-rows: entry[ks*4 + p][g] =
//   (half2(W[16ks+2p][g], W[16ks+2p+1][g]), half2(W[16ks+2p+8][g], ...+9))
// u64 stride BST=GP+4 (conflict-free per half-warp, same as prior rounds).
// OUTH: fp16 output (gather-source path).
template <int FP, int FS, int GP, bool PERK, bool RELUIN, bool HASB, bool OUTH,
          int SRCSEL, int DSTSEL>
__global__ void gemm_tc(const float* __restrict__ Xext,
                        const float* __restrict__ W, int Fl, int Gl,
                        const float* __restrict__ Bias, int Bk) {
    constexpr int NCH = GP / 8;
    constexpr int KST = FP / 16;
    constexpr int BST = GP + 4;          // u64 row stride of pair arrays

    extern __shared__ unsigned char dsm_raw[];
    uint2* Wph = (uint2*)dsm_raw;                   // (FP/4)*BST u64 entries
    uint2* Wpl = Wph + (FP / 4) * BST;
    float* Bsm = (float*)(Wpl + (FP / 4) * BST);

    const float* __restrict__ X = (SRCSEL < 0) ? Xext : sel_buf(SRCSEL);
    float* __restrict__ OUT = sel_buf(DSTSEL);

    const int kk = blockIdx.y;
    const int tid = threadIdx.x;
    const int wid = tid >> 5;
    const int lane = tid & 31;
    const int r0 = lane >> 2;    // 0..7
    const int c0 = lane & 3;     // 0..3

    // stage W as fp16 hi/lo, k-packed for m16n8k16 B fragments
    for (int i = tid; i < FP * GP; i += 256) {
        int f = i / GP, g = i % GP;
        float w = (f < Fl && g < Gl)
                      ? W[(size_t)kk * Fl * Gl + (size_t)f * Gl + g]
                      : 0.0f;
        __half hi = __float2half_rn(w);
        __half lo = __float2half_rn(w - __half2float(hi));
        int ks = f >> 4;
        int kc = f & 15;
        int pair = kc >> 1;          // 0..7
        int j = pair >> 2;           // uint2 slot
        int row = ks * 4 + (pair & 3);
        int hp = kc & 1;
        size_t hidx = ((size_t)(row * BST + g) * 2 + j) * 2 + hp;
        ((__half*)Wph)[hidx] = hi;
        ((__half*)Wpl)[hidx] = lo;
    }
    if (tid < GP) Bsm[tid] = (HASB && tid < Gl) ? Bias[(size_t)kk * Bk + tid] : 0.0f;
    __syncthreads();

    const int mbase = blockIdx.x * 256 + wid * 32;

    // row pointers: r0, r0+8 (tile 0), r0+16, r0+24 (tile 1); clamp loads.
    const float* xp[4];
#pragma unroll
    for (int t = 0; t < 4; t++) {
        int n = mbase + t * 8 + r0;
        int nc = n < NN ? n : NN - 1;
        xp[t] = X + (PERK ? ((size_t)kk * NN + nc) * FS : (size_t)nc * FS);
    }

    float acc[2][NCH][4];
#pragma unroll
    for (int t = 0; t < 2; t++)
#pragma unroll
        for (int nc = 0; nc < NCH; nc++)
#pragma unroll
            for (int q = 0; q < 4; q++) acc[t][nc][q] = 0.0f;

#pragma unroll
    for (int ks = 0; ks < KST; ks++) {
        const int kb = ks * 16;
        uint32_t ahi[2][4], alo[2][4];
#pragma unroll
        for (int t = 0; t < 2; t++) {
            // a0: row r0+16t, k{2c0,2c0+1}; a1: row r0+8+16t same k;
            // a2/a3: k += 8.
            float2 pA0 = *(const float2*)(xp[2 * t + 0] + kb + 2 * c0);
            float2 pB0 = *(const float2*)(xp[2 * t + 1] + kb + 2 * c0);
            float2 pA1 = *(const float2*)(xp[2 * t + 0] + kb + 2 * c0 + 8);
            float2 pB1 = *(const float2*)(xp[2 * t + 1] + kb + 2 * c0 + 8);
            float2 vv[4] = {pA0, pB0, pA1, pB1};
#pragma unroll
            for (int q = 0; q < 4; q++) {
                float vx = vv[q].x, vy = vv[q].y;
                if (RELUIN) { vx = fmaxf(vx, 0.f); vy = fmaxf(vy, 0.f); }
                __half2 hi2 = __floats2half2_rn(vx, vy);
                float2 hf = __half22float2(hi2);
                __half2 lo2 = __floats2half2_rn(vx - hf.x, vy - hf.y);
                ahi[t][q] = h2u(hi2);
                alo[t][q] = h2u(lo2);
            }
        }
#pragma unroll
        for (int nc = 0; nc < NCH; nc++) {
            const int bidx = (ks * 4 + c0) * BST + nc * 8 + r0;
            uint2 bh = Wph[bidx];
            uint2 bl = Wpl[bidx];
#pragma unroll
            for (int t = 0; t < 2; t++) {
                mma16(acc[t][nc], ahi[t], bh.x, bh.y);
                mma16(acc[t][nc], alo[t], bh.x, bh.y);
                mma16(acc[t][nc], ahi[t], bl.x, bl.y);
            }
        }
    }

#pragma unroll
    for (int t = 0; t < 2; t++) {
#pragma unroll
        for (int nc = 0; nc < NCH; nc++) {
            const int col = nc * 8 + 2 * c0;
            const float bx = Bsm[col], by = Bsm[col + 1];
            const int rowA = mbase + t * 16 + r0;
            const int rowB = rowA + 8;
            if (rowA < NN) {
                float vx = acc[t][nc][0] + bx, vy = acc[t][nc][1] + by;
                if (OUTH) {
                    __half2* o = (__half2*)((__half*)OUT +
                        ((size_t)kk * NN + rowA) * GP + col);
                    *o = __floats2half2_rn(vx, vy);
                } else {
                    *(float2*)(OUT + ((size_t)kk * NN + rowA) * GP + col) =
                        make_float2(vx, vy);
                }
            }
            if (rowB < NN) {
                float vx = acc[t][nc][2] + bx, vy = acc[t][nc][3] + by;
                if (OUTH) {
                    __half2* o = (__half2*)((__half*)OUT +
                        ((size_t)kk * NN + rowB) * GP + col);
                    *o = __floats2half2_rn(vx, vy);
                } else {
                    *(float2*)(OUT + ((size_t)kk * NN + rowB) * GP + col) =
                        make_float2(vx, vy);
                }
            }
        }
    }
}

static inline int gemm_smem_bytes(int FP, int GP) {
    return 2 * (FP / 4) * (GP + 4) * 8 + GP * 4;   // all < 48 KB now
}

// ---------------- CSR gather (fp16 src): dst[k,n] += sum norm*src[k,row] -----
template <int G4, int SRCSEL, int DSTSEL, bool COMBINE>
__global__ void gather_kernel() {
    const __half* __restrict__ src = (const __half*)sel_buf(SRCSEL);
    float* __restrict__ dst = sel_buf(DSTSEL);

    constexpr int ITEMS = KK * G4;
    const long long t = blockIdx.x * (long long)blockDim.x + threadIdx.x;
    const int n = (int)(t / ITEMS);
    if (n >= NN) return;
    const int rem = (int)(t - (long long)n * ITEMS);
    const int k = rem / G4;
    const int j = rem - k * G4;

    int p = g_off[n];
    const int end = g_off[n + 1];

    const __half* srcb = src + (size_t)k * NN * (G4 * 4);
    float4 acc = make_float4(0.f, 0.f, 0.f, 0.f);

#define GATH_LOAD(vv, ee)                                                     \
    {                                                                         \
        const __half2* hp = (const __half2*)(srcb +                           \
            (size_t)(ee).x * (G4 * 4) + j * 4);                               \
        float2 a = __half22float2(hp[0]);                                     \
        float2 b = __half22float2(hp[1]);                                     \
        vv = make_float4(a.x, a.y, b.x, b.y);                                 \
    }

    for (; p + 3 < end; p += 4) {
        int2 e0 = g_edge[p];
        int2 e1 = g_edge[p + 1];
        int2 e2 = g_edge[p + 2];
        int2 e3 = g_edge[p + 3];
        float4 v0, v1, v2, v3;
        GATH_LOAD(v0, e0) GATH_LOAD(v1, e1) GATH_LOAD(v2, e2) GATH_LOAD(v3, e3)
        float n0 = __int_as_float(e0.y);
        float n1 = __int_as_float(e1.y);
        float n2 = __int_as_float(e2.y);
        float n3 = __int_as_float(e3.y);
        acc.x += v0.x * n0 + v1.x * n1 + v2.x * n2 + v3.x * n3;
        acc.y += v0.y * n0 + v1.y * n1 + v2.y * n2 + v3.y * n3;
        acc.z += v0.z * n0 + v1.z * n1 + v2.z * n2 + v3.z * n3;
        acc.w += v0.w * n0 + v1.w * n1 + v2.w * n2 + v3.w * n3;
    }
    for (; p < end; p++) {
        int2 e0 = g_edge[p];
        float4 v0;
        GATH_LOAD(v0, e0)
        float n0 = __int_as_float(e0.y);
        acc.x += v0.x * n0; acc.y += v0.y * n0;
        acc.z += v0.z * n0; acc.w += v0.w * n0;
    }
#undef GATH_LOAD

    float4* dp = (float4*)(dst + ((size_t)k * NN + n) * (G4 * 4)) + j;
    float4 cur = *dp;
    cur.x += acc.x; cur.y += acc.y; cur.z += acc.z; cur.w += acc.w;

    if (COMBINE) {
        float4 r = make_float4(fmaxf(cur.x, 0.f), fmaxf(cur.y, 0.f),
                               fmaxf(cur.z, 0.f), fmaxf(cur.w, 0.f));
        float4 o;
        o.x = __shfl_xor_sync(0xFFFFFFFFu, r.x, 16);
        o.y = __shfl_xor_sync(0xFFFFFFFFu, r.y, 16);
        o.z = __shfl_xor_sync(0xFFFFFFFFu, r.z, 16);
        o.w = __shfl_xor_sync(0xFFFFFFFFu, r.w, 16);
        if (k == 0) {
            float4 hv = make_float4(0.5f * (r.x + o.x), 0.5f * (r.y + o.y),
                                    0.5f * (r.z + o.z), 0.5f * (r.w + o.w));
            *((float4*)(g_h + (size_t)n * 64) + j) = hv;
        }
    } else {
        *dp = cur;
    }
}

// ---------------- final: mean_k relu + log_softmax (C=41, stride 48) ---------
__global__ void final_kernel(float* __restrict__ out) {
    const int warp = (int)((blockIdx.x * (size_t)blockDim.x + threadIdx.x) >> 5);
    const int lane = threadIdx.x & 31;
    if (warp >= NN) return;

    const size_t b0 = (size_t)warp * 48;
    const size_t b1 = ((size_t)NN + warp) * 48;

    float v1 = -1e30f, v2 = -1e30f;
    if (lane < 41)
        v1 = 0.5f * (fmaxf(g_bufC[b0 + lane], 0.f) + fmaxf(g_bufC[b1 + lane], 0.f));
    if (lane + 32 < 41)
        v2 = 0.5f * (fmaxf(g_bufC[b0 + lane + 32], 0.f) + fmaxf(g_bufC[b1 + lane + 32], 0.f));

    float m = fmaxf(v1, v2);
#pragma unroll
    for (int o = 16; o; o >>= 1) m = fmaxf(m, __shfl_xor_sync(0xFFFFFFFFu, m, o));

    float s = 0.f;
    if (lane < 41) s += expf(v1 - m);
    if (lane + 32 < 41) s += expf(v2 - m);
#pragma unroll
    for (int o = 16; o; o >>= 1) s += __shfl_xor_sync(0xFFFFFFFFu, s, o);

    const float l = m + logf(s);
    if (lane < 41) out[(size_t)warp * 41 + lane] = v1 - l;
    if (lane + 32 < 41) out[(size_t)warp * 41 + lane + 32] = v2 - l;
}

// ---------------- host driver: 3-stream overlapped schedule ------------------
extern "C" void kernel_launch(void* const* d_in, const int* in_sizes, int n_in,
                              void* d_out, int out_size) {
    const float* x       = (const float*)d_in[0];
    const int*   ei      = (const int*)d_in[1];   // int32 (JAX x64 disabled)
    const float* w1_init = (const float*)d_in[2];
    const float* w1_mid  = (const float*)d_in[3];  // [1,K,64,64]
    const float* w1_root = (const float*)d_in[4];  // [2,K,128,64]
    const float* b1      = (const float*)d_in[5];  // [2,K,1,64]
    const float* w2_init = (const float*)d_in[6];
    const float* w2_mid  = (const float*)d_in[7];  // [1,K,41,41]
    const float* w2_root = (const float*)d_in[8];  // [2,K,64,41]
    const float* b2      = (const float*)d_in[9];  // [2,K,1,41]
    float* out = (float*)d_out;
    const int E = in_sizes[1] / 2;

    static bool inited = false;
    static cudaStream_t s1, s2;
    static cudaEvent_t evFork, evFill, evG2, evG4, evCH, evG6, evG8, evJ1;
    if (!inited) {
        cudaStreamCreateWithFlags(&s1, cudaStreamNonBlocking);
        cudaStreamCreateWithFlags(&s2, cudaStreamNonBlocking);
        cudaEventCreateWithFlags(&evFork, cudaEventDisableTiming);
        cudaEventCreateWithFlags(&evFill, cudaEventDisableTiming);
        cudaEventCreateWithFlags(&evG2,   cudaEventDisableTiming);
        cudaEventCreateWithFlags(&evG4,   cudaEventDisableTiming);
        cudaEventCreateWithFlags(&evCH,   cudaEventDisableTiming);
        cudaEventCreateWithFlags(&evG6,   cudaEventDisableTiming);
        cudaEventCreateWithFlags(&evG8,   cudaEventDisableTiming);
        cudaEventCreateWithFlags(&evJ1,   cudaEventDisableTiming);
        inited = true;
    }

    const int nb_n  = (NN + 255) / 256;
    const int nb_e  = (E + 255) / 256;
    const int nb_g1 = (int)(((long long)NN * 32 + 255) / 256);  // G4=16
    const int nb_g2 = (int)(((long long)NN * 24 + 255) / 256);  // G4=12

    const dim3 g_tc((NN + 255) / 256, KK);

    const int sm_128_64 = gemm_smem_bytes(128, 64);  // 35,072 B (< 48 KB)
    const int sm_64_64  = gemm_smem_bytes(64, 64);
    const int sm_64_48  = gemm_smem_bytes(64, 48);
    const int sm_48_48  = gemm_smem_bytes(48, 48);

    // ---- fork side streams from the (capturing) origin stream --------------
    cudaEventRecord(evFork, 0);
    cudaStreamWaitEvent(s1, evFork, 0);
    cudaStreamWaitEvent(s2, evFork, 0);

    // s2: CSR/prep chain (small grids; hides under the big GEMMs)
    zero_cnt_kernel<<<nb_n, 256, 0, s2>>>();
    count_kernel<<<nb_e, 256, 0, s2>>>(ei + E, E);
    dinv_kernel<<<nb_n, 256, 0, s2>>>();
    scanA_kernel<<<NB_SCAN, SCAN_CHUNK, 0, s2>>>();
    scanB_kernel<<<1, 256, 0, s2>>>();
    scanC_kernel<<<NB_SCAN, SCAN_CHUNK, 0, s2>>>();
    fill_kernel<<<nb_e, 256, 0, s2>>>(ei, E);
    cudaEventRecord(evFill, s2);

    // s1: root0 (x->bufA fp32), root1 (x->bufC fp32)
    gemm_tc<128, 128, 64, false, false, true, false, -1, 1>
        <<<g_tc, 256, sm_128_64, s1>>>(x, w1_root, 128, 64, b1, 64);
    cudaEventRecord(evG2, s1);
    gemm_tc<128, 128, 64, false, false, true, false, -1, 3>
        <<<g_tc, 256, sm_128_64, s1>>>(x, w1_root + (size_t)2 * 128 * 64,
                                       128, 64, b1 + 2 * 64, 64);
    cudaEventRecord(evG4, s1);

    // s0 (origin): init GEMM (x->bufT fp16), then the dependent chain
    gemm_tc<128, 128, 64, false, false, false, true, -1, 0>
        <<<g_tc, 256, sm_128_64>>>(x, w1_init, 128, 64, nullptr, 0);
    cudaStreamWaitEvent(0, evG2, 0);
    cudaStreamWaitEvent(0, evFill, 0);
    gather_kernel<16, 0, 1, false><<<nb_g1, 256>>>();     // bufT(h16) -> bufA
    gemm_tc<64, 64, 64, true, true, false, true, 1, 0><<<g_tc, 256, sm_64_64>>>(
        nullptr, w1_mid, 64, 64, nullptr, 0);             // mid: bufA -> bufT h16
    cudaStreamWaitEvent(0, evG4, 0);
    gather_kernel<16, 0, 3, true><<<nb_g1, 256>>>();      // bufT+bufC -> h (fused)
    cudaEventRecord(evCH, 0);

    // s1: layer-2 root GEMMs (depend on h)
    cudaStreamWaitEvent(s1, evCH, 0);
    gemm_tc<64, 64, 48, false, false, true, false, 2, 1>
        <<<g_tc, 256, sm_64_48, s1>>>(nullptr, w2_root, 64, 41, b2, 41);
    cudaEventRecord(evG6, s1);
    gemm_tc<64, 64, 48, false, false, true, false, 2, 3>
        <<<g_tc, 256, sm_64_48, s1>>>(nullptr, w2_root + (size_t)2 * 64 * 41,
                                      64, 41, b2 + 2 * 41, 41);
    cudaEventRecord(evG8, s1);                            // h -> bufC

    // s0: layer-2 chain
    gemm_tc<64, 64, 48, false, false, false, true, 2, 0><<<g_tc, 256, sm_64_48>>>(
        nullptr, w2_init, 64, 41, nullptr, 0);            // h -> bufT h16
    cudaStreamWaitEvent(0, evG6, 0);
    gather_kernel<12, 0, 1, false><<<nb_g2, 256>>>();     // bufT(h16) -> bufA
    gemm_tc<48, 48, 48, true, true, false, true, 1, 0><<<g_tc, 256, sm_48_48>>>(
        nullptr, w2_mid, 41, 41, nullptr, 0);             // mid2: bufA -> bufT h16
    cudaStreamWaitEvent(0, evG8, 0);
    gather_kernel<12, 0, 3, false><<<nb_g2, 256>>>();     // bufT(h16) -> bufC
    final_kernel<<<(NN * 32 + 255) / 256, 256>>>(out);    // bufC -> out

    // ---- join side streams back into the origin stream ---------------------
    cudaEventRecord(evJ1, s1);
    cudaStreamWaitEvent(0, evJ1, 0);
    cudaStreamWaitEvent(0, evFill, 0);
}

// round 16
// speedup vs baseline: 1.5548x; 1.0112x over previous
#include <cuda_runtime.h>
#include <cuda_fp16.h>
#include <cstdint>
#include <cstring>

#define NN 100000
#define KK 2
#define EMAX 1600000
#define SCAN_CHUNK 512
#define NB_SCAN ((NN + SCAN_CHUNK - 1) / SCAN_CHUNK)   // 196

// ---------------- scratch (static device globals; no allocation) -------------
__device__ float g_dinv[NN];
__device__ int   g_cnt[NN];
__device__ int   g_off[NN + 1];
__device__ int   g_cur[NN];
__device__ int   g_bsum[256];
__device__ int   g_boff[256];
__device__ int2  g_edge[EMAX];                       // (row, norm), CSR by col
__device__ float g_bufT[(size_t)KK * NN * 64 + 64];  // fp16-packed gather src
__device__ float g_bufA[(size_t)KK * NN * 64 + 64];  // root terms (fp32)
__device__ float g_h[(size_t)NN * 64 + 64];          // layer-1 output (fp32)
__device__ float g_bufC[(size_t)KK * NN * 64 + 64];  // root terms (fp32)
__device__ float g_bufD[(size_t)KK * NN * 64 + 64];  // pure message sums (fp32)

__device__ __forceinline__ float* sel_buf(int s) {
    return s == 0 ? g_bufT
         : (s == 1 ? g_bufA
         : (s == 2 ? g_h
         : (s == 3 ? g_bufC : g_bufD)));
}

// ---------------- fp16 helpers -----------------------------------------------
__device__ __forceinline__ uint32_t h2u(__half2 h) {
    uint32_t u;
    memcpy(&u, &h, 4);
    return u;
}

// m16n8k16 f16 MMA, f32 accumulate
__device__ __forceinline__ void mma16(float* d, const uint32_t* a,
                                      uint32_t b0, uint32_t b1) {
    asm("mma.sync.aligned.m16n8k16.row.col.f32.f16.f16.f32 "
        "{%0,%1,%2,%3}, {%4,%5,%6,%7}, {%8,%9}, {%0,%1,%2,%3};"
        : "+f"(d[0]), "+f"(d[1]), "+f"(d[2]), "+f"(d[3])
        : "r"(a[0]), "r"(a[1]), "r"(a[2]), "r"(a[3]), "r"(b0), "r"(b1));
}

// ---------------- prep: degree, CSR build ------------------------------------
__global__ void zero_cnt_kernel() {
    int n = blockIdx.x * blockDim.x + threadIdx.x;
    if (n < NN) g_cnt[n] = 0;
}

__global__ void count_kernel(const int* __restrict__ col, int E) {
    int e = blockIdx.x * blockDim.x + threadIdx.x;
    if (e < E) atomicAdd(&g_cnt[col[e]], 1);
}

__global__ void dinv_kernel() {
    int n = blockIdx.x * blockDim.x + threadIdx.x;
    if (n < NN) {
        int c = g_cnt[n];
        g_dinv[n] = c > 0 ? rsqrtf((float)c) : 0.0f;
    }
}

__global__ void scanA_kernel() {
    __shared__ int s[SCAN_CHUNK];
    int t = threadIdx.x;
    int i = blockIdx.x * SCAN_CHUNK + t;
    s[t] = (i < NN) ? g_cnt[i] : 0;
    __syncthreads();
    for (int o = SCAN_CHUNK / 2; o > 0; o >>= 1) {
        if (t < o) s[t] += s[t + o];
        __syncthreads();
    }
    if (t == 0) g_bsum[blockIdx.x] = s[0];
}

__global__ void scanB_kernel() {
    __shared__ int s[256];
    int t = threadIdx.x;
    int val = (t < NB_SCAN) ? g_bsum[t] : 0;
    s[t] = val;
    __syncthreads();
    for (int o = 1; o < 256; o <<= 1) {
        int add = (t >= o) ? s[t - o] : 0;
        __syncthreads();
        s[t] += add;
        __syncthreads();
    }
    g_boff[t] = s[t] - val;
    if (t == NB_SCAN - 1) g_off[NN] = s[t];
}

__global__ void scanC_kernel() {
    __shared__ int s[SCAN_CHUNK];
    int t = threadIdx.x;
    int i = blockIdx.x * SCAN_CHUNK + t;
    int val = (i < NN) ? g_cnt[i] : 0;
    s[t] = val;
    __syncthreads();
    for (int o = 1; o < SCAN_CHUNK; o <<= 1) {
        int add = (t >= o) ? s[t - o] : 0;
        __syncthreads();
        s[t] += add;
        __syncthreads();
    }
    if (i < NN) {
        int excl = s[t] - val + g_boff[blockIdx.x];
        g_off[i] = excl;
        g_cur[i] = excl;
    }
}

__global__ void fill_kernel(const int* __restrict__ ei, int E) {
    int e = blockIdx.x * blockDim.x + threadIdx.x;
    if (e < E) {
        int r = ei[e];
        int c = ei[(size_t)E + e];
        float nrm = g_dinv[r] * g_dinv[c];
        int pos = atomicAdd(&g_cur[c], 1);
        g_edge[pos] = make_int2(r, __float_as_int(nrm));
    }
}

// ---------------- tensor-core GEMM (fp16 3-term split, m16n8k16) -------------
// RELU2: A = relu(src + g_bufD) — folds the pure-message buffer into the
// mid-GEMM input, breaking the root->gather RMW dependency.
// OUTH: fp16 output (gather-source path).
template <int FP, int FS, int GP, bool PERK, bool RELUIN, bool RELU2,
          bool HASB, bool OUTH, int SRCSEL, int DSTSEL>
__global__ void gemm_tc(const float* __restrict__ Xext,
                        const float* __restrict__ W, int Fl, int Gl,
                        const float* __restrict__ Bias, int Bk) {
    constexpr int NCH = GP / 8;
    constexpr int KST = FP / 16;
    constexpr int BST = GP + 4;          // u64 row stride of pair arrays

    extern __shared__ unsigned char dsm_raw[];
    uint2* Wph = (uint2*)dsm_raw;                   // (FP/4)*BST u64 entries
    uint2* Wpl = Wph + (FP / 4) * BST;
    float* Bsm = (float*)(Wpl + (FP / 4) * BST);

    const float* __restrict__ X = (SRCSEL < 0) ? Xext : sel_buf(SRCSEL);
    float* __restrict__ OUT = sel_buf(DSTSEL);

    const int kk = blockIdx.y;
    const int tid = threadIdx.x;
    const int wid = tid >> 5;
    const int lane = tid & 31;
    const int r0 = lane >> 2;    // 0..7
    const int c0 = lane & 3;     // 0..3

    // stage W as fp16 hi/lo, k-packed for m16n8k16 B fragments
    for (int i = tid; i < FP * GP; i += 256) {
        int f = i / GP, g = i % GP;
        float w = (f < Fl && g < Gl)
                      ? W[(size_t)kk * Fl * Gl + (size_t)f * Gl + g]
                      : 0.0f;
        __half hi = __float2half_rn(w);
        __half lo = __float2half_rn(w - __half2float(hi));
        int ks = f >> 4;
        int kc = f & 15;
        int pair = kc >> 1;          // 0..7
        int j = pair >> 2;           // uint2 slot
        int row = ks * 4 + (pair & 3);
        int hp = kc & 1;
        size_t hidx = ((size_t)(row * BST + g) * 2 + j) * 2 + hp;
        ((__half*)Wph)[hidx] = hi;
        ((__half*)Wpl)[hidx] = lo;
    }
    if (tid < GP) Bsm[tid] = (HASB && tid < Gl) ? Bias[(size_t)kk * Bk + tid] : 0.0f;
    __syncthreads();

    const int mbase = blockIdx.x * 256 + wid * 32;

    const float* xp[4];
    const float* xq[4];
#pragma unroll
    for (int t = 0; t < 4; t++) {
        int n = mbase + t * 8 + r0;
        int nc = n < NN ? n : NN - 1;
        size_t off = PERK ? ((size_t)kk * NN + nc) * FS : (size_t)nc * FS;
        xp[t] = X + off;
        if (RELU2) xq[t] = g_bufD + off;
    }

    float acc[2][NCH][4];
#pragma unroll
    for (int t = 0; t < 2; t++)
#pragma unroll
        for (int nc = 0; nc < NCH; nc++)
#pragma unroll
            for (int q = 0; q < 4; q++) acc[t][nc][q] = 0.0f;

#pragma unroll
    for (int ks = 0; ks < KST; ks++) {
        const int kb = ks * 16;
        uint32_t ahi[2][4], alo[2][4];
#pragma unroll
        for (int t = 0; t < 2; t++) {
            float2 pA0 = *(const float2*)(xp[2 * t + 0] + kb + 2 * c0);
            float2 pB0 = *(const float2*)(xp[2 * t + 1] + kb + 2 * c0);
            float2 pA1 = *(const float2*)(xp[2 * t + 0] + kb + 2 * c0 + 8);
            float2 pB1 = *(const float2*)(xp[2 * t + 1] + kb + 2 * c0 + 8);
            if (RELU2) {
                float2 q;
                q = *(const float2*)(xq[2 * t + 0] + kb + 2 * c0);
                pA0.x += q.x; pA0.y += q.y;
                q = *(const float2*)(xq[2 * t + 1] + kb + 2 * c0);
                pB0.x += q.x; pB0.y += q.y;
                q = *(const float2*)(xq[2 * t + 0] + kb + 2 * c0 + 8);
                pA1.x += q.x; pA1.y += q.y;
                q = *(const float2*)(xq[2 * t + 1] + kb + 2 * c0 + 8);
                pB1.x += q.x; pB1.y += q.y;
            }
            float2 vv[4] = {pA0, pB0, pA1, pB1};
#pragma unroll
            for (int q = 0; q < 4; q++) {
                float vx = vv[q].x, vy = vv[q].y;
                if (RELUIN) { vx = fmaxf(vx, 0.f); vy = fmaxf(vy, 0.f); }
                __half2 hi2 = __floats2half2_rn(vx, vy);
                float2 hf = __half22float2(hi2);
                __half2 lo2 = __floats2half2_rn(vx - hf.x, vy - hf.y);
                ahi[t][q] = h2u(hi2);
                alo[t][q] = h2u(lo2);
            }
        }
#pragma unroll
        for (int nc = 0; nc < NCH; nc++) {
            const int bidx = (ks * 4 + c0) * BST + nc * 8 + r0;
            uint2 bh = Wph[bidx];
            uint2 bl = Wpl[bidx];
#pragma unroll
            for (int t = 0; t < 2; t++) {
                mma16(acc[t][nc], ahi[t], bh.x, bh.y);
                mma16(acc[t][nc], alo[t], bh.x, bh.y);
                mma16(acc[t][nc], ahi[t], bl.x, bl.y);
            }
        }
    }

#pragma unroll
    for (int t = 0; t < 2; t++) {
#pragma unroll
        for (int nc = 0; nc < NCH; nc++) {
            const int col = nc * 8 + 2 * c0;
            const float bx = Bsm[col], by = Bsm[col + 1];
            const int rowA = mbase + t * 16 + r0;
            const int rowB = rowA + 8;
            if (rowA < NN) {
                float vx = acc[t][nc][0] + bx, vy = acc[t][nc][1] + by;
                if (OUTH) {
                    __half2* o = (__half2*)((__half*)OUT +
                        ((size_t)kk * NN + rowA) * GP + col);
                    *o = __floats2half2_rn(vx, vy);
                } else {
                    *(float2*)(OUT + ((size_t)kk * NN + rowA) * GP + col) =
                        make_float2(vx, vy);
                }
            }
            if (rowB < NN) {
                float vx = acc[t][nc][2] + bx, vy = acc[t][nc][3] + by;
                if (OUTH) {
                    __half2* o = (__half2*)((__half*)OUT +
                        ((size_t)kk * NN + rowB) * GP + col);
                    *o = __floats2half2_rn(vx, vy);
                } else {
                    *(float2*)(OUT + ((size_t)kk * NN + rowB) * GP + col) =
                        make_float2(vx, vy);
                }
            }
        }
    }
}

static inline int gemm_smem_bytes(int FP, int GP) {
    return 2 * (FP / 4) * (GP + 4) * 8 + GP * 4;   // all < 48 KB
}

// ---------------- CSR gather (fp16 src) --------------------------------------
// PUREMSG: write raw message sum (no dst read) — breaks root->gather dep.
// COMBINE: read dst (root term), add, relu, k-mean via shfl_xor(16) -> g_h.
// default: RMW accumulate into dst.
template <int G4, int SRCSEL, int DSTSEL, bool COMBINE, bool PUREMSG>
__global__ void gather_kernel() {
    const __half* __restrict__ src = (const __half*)sel_buf(SRCSEL);
    float* __restrict__ dst = sel_buf(DSTSEL);

    constexpr int ITEMS = KK * G4;
    const long long t = blockIdx.x * (long long)blockDim.x + threadIdx.x;
    const int n = (int)(t / ITEMS);
    if (n >= NN) return;
    const int rem = (int)(t - (long long)n * ITEMS);
    const int k = rem / G4;
    const int j = rem - k * G4;

    int p = g_off[n];
    const int end = g_off[n + 1];

    const __half* srcb = src + (size_t)k * NN * (G4 * 4);
    float4 acc = make_float4(0.f, 0.f, 0.f, 0.f);

#define GATH_LOAD(vv, ee)                                                     \
    {                                                                         \
        const __half2* hp = (const __half2*)(srcb +                           \
            (size_t)(ee).x * (G4 * 4) + j * 4);                               \
        float2 a = __half22float2(hp[0]);                                     \
        float2 b = __half22float2(hp[1]);                                     \
        vv = make_float4(a.x, a.y, b.x, b.y);                                 \
    }

    for (; p + 3 < end; p += 4) {
        int2 e0 = g_edge[p];
        int2 e1 = g_edge[p + 1];
        int2 e2 = g_edge[p + 2];
        int2 e3 = g_edge[p + 3];
        float4 v0, v1, v2, v3;
        GATH_LOAD(v0, e0) GATH_LOAD(v1, e1) GATH_LOAD(v2, e2) GATH_LOAD(v3, e3)
        float n0 = __int_as_float(e0.y);
        float n1 = __int_as_float(e1.y);
        float n2 = __int_as_float(e2.y);
        float n3 = __int_as_float(e3.y);
        acc.x += v0.x * n0 + v1.x * n1 + v2.x * n2 + v3.x * n3;
        acc.y += v0.y * n0 + v1.y * n1 + v2.y * n2 + v3.y * n3;
        acc.z += v0.z * n0 + v1.z * n1 + v2.z * n2 + v3.z * n3;
        acc.w += v0.w * n0 + v1.w * n1 + v2.w * n2 + v3.w * n3;
    }
    for (; p < end; p++) {
        int2 e0 = g_edge[p];
        float4 v0;
        GATH_LOAD(v0, e0)
        float n0 = __int_as_float(e0.y);
        acc.x += v0.x * n0; acc.y += v0.y * n0;
        acc.z += v0.z * n0; acc.w += v0.w * n0;
    }
#undef GATH_LOAD

    float4* dp = (float4*)(dst + ((size_t)k * NN + n) * (G4 * 4)) + j;

    if (PUREMSG) {
        *dp = acc;
        return;
    }

    float4 cur = *dp;
    cur.x += acc.x; cur.y += acc.y; cur.z += acc.z; cur.w += acc.w;

    if (COMBINE) {
        float4 r = make_float4(fmaxf(cur.x, 0.f), fmaxf(cur.y, 0.f),
                               fmaxf(cur.z, 0.f), fmaxf(cur.w, 0.f));
        float4 o;
        o.x = __shfl_xor_sync(0xFFFFFFFFu, r.x, 16);
        o.y = __shfl_xor_sync(0xFFFFFFFFu, r.y, 16);
        o.z = __shfl_xor_sync(0xFFFFFFFFu, r.z, 16);
        o.w = __shfl_xor_sync(0xFFFFFFFFu, r.w, 16);
        if (k == 0) {
            float4 hv = make_float4(0.5f * (r.x + o.x), 0.5f * (r.y + o.y),
                                    0.5f * (r.z + o.z), 0.5f * (r.w + o.w));
            *((float4*)(g_h + (size_t)n * 64) + j) = hv;
        }
    } else {
        *dp = cur;
    }
}

// ---------------- final: mean_k relu + log_softmax (C=41, stride 48) ---------
__global__ void final_kernel(float* __restrict__ out) {
    const int warp = (int)((blockIdx.x * (size_t)blockDim.x + threadIdx.x) >> 5);
    const int lane = threadIdx.x & 31;
    if (warp >= NN) return;

    const size_t b0 = (size_t)warp * 48;
    const size_t b1 = ((size_t)NN + warp) * 48;

    float v1 = -1e30f, v2 = -1e30f;
    if (lane < 41)
        v1 = 0.5f * (fmaxf(g_bufC[b0 + lane], 0.f) + fmaxf(g_bufC[b1 + lane], 0.f));
    if (lane + 32 < 41)
        v2 = 0.5f * (fmaxf(g_bufC[b0 + lane + 32], 0.f) + fmaxf(g_bufC[b1 + lane + 32], 0.f));

    float m = fmaxf(v1, v2);
#pragma unroll
    for (int o = 16; o; o >>= 1) m = fmaxf(m, __shfl_xor_sync(0xFFFFFFFFu, m, o));

    float s = 0.f;
    if (lane < 41) s += expf(v1 - m);
    if (lane + 32 < 41) s += expf(v2 - m);
#pragma unroll
    for (int o = 16; o; o >>= 1) s += __shfl_xor_sync(0xFFFFFFFFu, s, o);

    const float l = m + logf(s);
    if (lane < 41) out[(size_t)warp * 41 + lane] = v1 - l;
    if (lane + 32 < 41) out[(size_t)warp * 41 + lane + 32] = v2 - l;
}

// ---------------- host driver: 3-stream overlapped schedule ------------------
extern "C" void kernel_launch(void* const* d_in, const int* in_sizes, int n_in,
                              void* d_out, int out_size) {
    const float* x       = (const float*)d_in[0];
    const int*   ei      = (const int*)d_in[1];   // int32 (JAX x64 disabled)
    const float* w1_init = (const float*)d_in[2];
    const float* w1_mid  = (const float*)d_in[3];  // [1,K,64,64]
    const float* w1_root = (const float*)d_in[4];  // [2,K,128,64]
    const float* b1      = (const float*)d_in[5];  // [2,K,1,64]
    const float* w2_init = (const float*)d_in[6];
    const float* w2_mid  = (const float*)d_in[7];  // [1,K,41,41]
    const float* w2_root = (const float*)d_in[8];  // [2,K,64,41]
    const float* b2      = (const float*)d_in[9];  // [2,K,1,41]
    float* out = (float*)d_out;
    const int E = in_sizes[1] / 2;

    static bool inited = false;
    static cudaStream_t s1, s2;
    static cudaEvent_t evFork, evFill, evR0, evR1, evCH, evR2, evR3, evJ1;
    if (!inited) {
        cudaStreamCreateWithFlags(&s1, cudaStreamNonBlocking);
        cudaStreamCreateWithFlags(&s2, cudaStreamNonBlocking);
        cudaEventCreateWithFlags(&evFork, cudaEventDisableTiming);
        cudaEventCreateWithFlags(&evFill, cudaEventDisableTiming);
        cudaEventCreateWithFlags(&evR0,   cudaEventDisableTiming);
        cudaEventCreateWithFlags(&evR1,   cudaEventDisableTiming);
        cudaEventCreateWithFlags(&evCH,   cudaEventDisableTiming);
        cudaEventCreateWithFlags(&evR2,   cudaEventDisableTiming);
        cudaEventCreateWithFlags(&evR3,   cudaEventDisableTiming);
        cudaEventCreateWithFlags(&evJ1,   cudaEventDisableTiming);
        inited = true;
    }

    const int nb_n  = (NN + 255) / 256;
    const int nb_e  = (E + 255) / 256;
    const int nb_g1 = (int)(((long long)NN * 32 + 255) / 256);  // G4=16
    const int nb_g2 = (int)(((long long)NN * 24 + 255) / 256);  // G4=12

    const dim3 g_tc((NN + 255) / 256, KK);

    const int sm_128_64 = gemm_smem_bytes(128, 64);
    const int sm_64_64  = gemm_smem_bytes(64, 64);
    const int sm_64_48  = gemm_smem_bytes(64, 48);
    const int sm_48_48  = gemm_smem_bytes(48, 48);

    // ---- fork side streams from the (capturing) origin stream --------------
    cudaEventRecord(evFork, 0);
    cudaStreamWaitEvent(s1, evFork, 0);
    cudaStreamWaitEvent(s2, evFork, 0);

    // s2: CSR/prep chain (small grids; hides under the big GEMMs)
    zero_cnt_kernel<<<nb_n, 256, 0, s2>>>();
    count_kernel<<<nb_e, 256, 0, s2>>>(ei + E, E);
    dinv_kernel<<<nb_n, 256, 0, s2>>>();
    scanA_kernel<<<NB_SCAN, SCAN_CHUNK, 0, s2>>>();
    scanB_kernel<<<1, 256, 0, s2>>>();
    scanC_kernel<<<NB_SCAN, SCAN_CHUNK, 0, s2>>>();
    fill_kernel<<<nb_e, 256, 0, s2>>>(ei, E);
    cudaEventRecord(evFill, s2);

    // s1: root0 (x->bufA fp32), root1 (x->bufC fp32)
    gemm_tc<128, 128, 64, false, false, false, true, false, -1, 1>
        <<<g_tc, 256, sm_128_64, s1>>>(x, w1_root, 128, 64, b1, 64);
    cudaEventRecord(evR0, s1);
    gemm_tc<128, 128, 64, false, false, false, true, false, -1, 3>
        <<<g_tc, 256, sm_128_64, s1>>>(x, w1_root + (size_t)2 * 128 * 64,
                                       128, 64, b1 + 2 * 64, 64);
    cudaEventRecord(evR1, s1);

    // s0: init GEMM (x->bufT fp16), then the dependent chain.
    // GA1 is PURE-MSG -> depends only on init+fill, overlaps root0/root1.
    gemm_tc<128, 128, 64, false, false, false, false, true, -1, 0>
        <<<g_tc, 256, sm_128_64>>>(x, w1_init, 128, 64, nullptr, 0);
    cudaStreamWaitEvent(0, evFill, 0);
    gather_kernel<16, 0, 4, false, true><<<nb_g1, 256>>>();   // bufT -> bufD (msg)
    cudaStreamWaitEvent(0, evR0, 0);
    gemm_tc<64, 64, 64, true, true, true, false, true, 1, 0>  // relu(bufA+bufD)
        <<<g_tc, 256, sm_64_64>>>(nullptr, w1_mid, 64, 64, nullptr, 0);
    cudaStreamWaitEvent(0, evR1, 0);
    gather_kernel<16, 0, 3, true, false><<<nb_g1, 256>>>();   // + bufC(root1) -> h
    cudaEventRecord(evCH, 0);

    // s1: layer-2 root GEMMs (depend on h; also bufA/bufC free after evCH)
    cudaStreamWaitEvent(s1, evCH, 0);
    gemm_tc<64, 64, 48, false, false, false, true, false, 2, 1>
        <<<g_tc, 256, sm_64_48, s1>>>(nullptr, w2_root, 64, 41, b2, 41);
    cudaEventRecord(evR2, s1);
    gemm_tc<64, 64, 48, false, false, false, true, false, 2, 3>
        <<<g_tc, 256, sm_64_48, s1>>>(nullptr, w2_root + (size_t)2 * 64 * 41,
                                      64, 41, b2 + 2 * 41, 41);
    cudaEventRecord(evR3, s1);

    // s0: layer-2 chain; GA3 is PURE-MSG -> overlaps the root2 GEMMs.
    gemm_tc<64, 64, 48, false, false, false, false, true, 2, 0>
        <<<g_tc, 256, sm_64_48>>>(nullptr, w2_init, 64, 41, nullptr, 0);
    gather_kernel<12, 0, 4, false, true><<<nb_g2, 256>>>();   // bufT -> bufD (msg)
    cudaStreamWaitEvent(0, evR2, 0);
    gemm_tc<48, 48, 48, true, true, true, false, true, 1, 0>  // relu(bufA+bufD)
        <<<g_tc, 256, sm_48_48>>>(nullptr, w2_mid, 41, 41, nullptr, 0);
    cudaStreamWaitEvent(0, evR3, 0);
    gather_kernel<12, 0, 3, false, false><<<nb_g2, 256>>>();  // RMW bufC(root2_1)
    final_kernel<<<(NN * 32 + 255) / 256, 256>>>(out);        // bufC -> out

    // ---- join side streams back into the origin stream ---------------------
    cudaEventRecord(evJ1, s1);
    cudaStreamWaitEvent(0, evJ1, 0);
    cudaStreamWaitEvent(0, evFill, 0);
}